// round 1
// baseline (speedup 1.0000x reference)
#include <cuda_runtime.h>
#include <math.h>

#define Bb 8
#define Nn 4096
#define Dd 512
#define Mm (Bb*Nn)    // 32768 rows
#define Hh (Dd/2)     // 256
#define SPLITK 4

// Scratch (allocation-free rule: __device__ globals)
__device__ float g_q[(size_t)Mm*Dd];
__device__ float g_k[(size_t)Mm*Dd];
__device__ float g_v[(size_t)Mm*Dd];
__device__ float g_kv[(size_t)Bb*Dd*Dd];

// ---------------------------------------------------------------------------
// C[M,512] = A[M,512] @ W[512,512]^T + bias   (128x128x16 tile, 8x8 per thread)
// ---------------------------------------------------------------------------
__global__ __launch_bounds__(256) void gemm_nt128(
    const float* __restrict__ A, const float* __restrict__ W,
    const float* __restrict__ bias, float* __restrict__ C)
{
    __shared__ float As[16][128];
    __shared__ float Bs[16][128];
    const int tid = threadIdx.x;
    const int tx = tid & 15, ty = tid >> 4;
    const int m0 = blockIdx.y * 128;
    const int n0 = blockIdx.x * 128;
    float acc[8][8] = {};

    for (int k0 = 0; k0 < Dd; k0 += 16) {
#pragma unroll
        for (int r = 0; r < 2; r++) {
            int e  = tid + r * 256;
            int m  = e >> 2;
            int kq = (e & 3) * 4;
            float4 a = *reinterpret_cast<const float4*>(A + (size_t)(m0 + m) * Dd + k0 + kq);
            As[kq+0][m] = a.x; As[kq+1][m] = a.y; As[kq+2][m] = a.z; As[kq+3][m] = a.w;
            float4 w = *reinterpret_cast<const float4*>(W + (size_t)(n0 + m) * Dd + k0 + kq);
            Bs[kq+0][m] = w.x; Bs[kq+1][m] = w.y; Bs[kq+2][m] = w.z; Bs[kq+3][m] = w.w;
        }
        __syncthreads();
#pragma unroll
        for (int kk = 0; kk < 16; kk++) {
            float a[8], b[8];
            *(float4*)&a[0] = *(const float4*)&As[kk][ty*8];
            *(float4*)&a[4] = *(const float4*)&As[kk][ty*8+4];
            *(float4*)&b[0] = *(const float4*)&Bs[kk][tx*8];
            *(float4*)&b[4] = *(const float4*)&Bs[kk][tx*8+4];
#pragma unroll
            for (int i = 0; i < 8; i++)
#pragma unroll
                for (int j = 0; j < 8; j++) acc[i][j] += a[i] * b[j];
        }
        __syncthreads();
    }

    float bcol[8];
#pragma unroll
    for (int j = 0; j < 8; j++) bcol[j] = bias[n0 + tx*8 + j];
#pragma unroll
    for (int i = 0; i < 8; i++) {
        int m = m0 + ty*8 + i;
        float4 o0, o1;
        o0.x = acc[i][0] + bcol[0]; o0.y = acc[i][1] + bcol[1];
        o0.z = acc[i][2] + bcol[2]; o0.w = acc[i][3] + bcol[3];
        o1.x = acc[i][4] + bcol[4]; o1.y = acc[i][5] + bcol[5];
        o1.z = acc[i][6] + bcol[6]; o1.w = acc[i][7] + bcol[7];
        *(float4*)(C + (size_t)m * Dd + n0 + tx*8)     = o0;
        *(float4*)(C + (size_t)m * Dd + n0 + tx*8 + 4) = o1;
    }
}

// ---------------------------------------------------------------------------
// Rotary + scaling epilogue. One block per row; thread i handles pair (i, i+256).
// ---------------------------------------------------------------------------
__global__ __launch_bounds__(256) void epilogue_rope(
    const float* __restrict__ coords, const float* __restrict__ weights,
    const float* __restrict__ Wrot)
{
    const int row = blockIdx.x;
    const int i = threadIdx.x;   // 0..255
    const float c0 = coords[row*3+0], c1 = coords[row*3+1], c2 = coords[row*3+2];
    const float p = c0*Wrot[i*3+0] + c1*Wrot[i*3+1] + c2*Wrot[i*3+2];
    float s, c;
    sincosf(p, &s, &c);
    const float scale = 0.04419417382415922f;   // 1/sqrt(512)
    const size_t base = (size_t)row * Dd;

    float qa = g_q[base + i], qb = g_q[base + i + Hh];
    g_q[base + i]      = (qa*c - qb*s) * scale;
    g_q[base + i + Hh] = (qa*s + qb*c) * scale;

    float ka = g_k[base + i], kb = g_k[base + i + Hh];
    g_k[base + i]      = ka*c - kb*s;
    g_k[base + i + Hh] = ka*s + kb*c;

    const float w = weights[row];
    g_v[base + i]      *= w;
    g_v[base + i + Hh] *= w;
}

// ---------------------------------------------------------------------------
__global__ __launch_bounds__(256) void zero_kv_kernel()
{
    size_t i = (size_t)blockIdx.x * 256 + threadIdx.x;
    g_kv[i] = 0.0f;
}

// ---------------------------------------------------------------------------
// kv[b,d,e] = sum_n K[b,n,d] * V[b,n,e]   (64x64x16 tile, split-K over n, atomicAdd)
// ---------------------------------------------------------------------------
__global__ __launch_bounds__(256) void kv_gemm()
{
    __shared__ float As[16][64];
    __shared__ float Bs[16][64];
    const int tid = threadIdx.x;
    const int tx = tid & 15, ty = tid >> 4;
    const int b = blockIdx.z >> 2;           // / SPLITK
    const int chunk = blockIdx.z & 3;
    const int d0 = blockIdx.y * 64;
    const int e0 = blockIdx.x * 64;
    const float* Kp = g_k + (size_t)b * Nn * Dd;
    const float* Vp = g_v + (size_t)b * Nn * Dd;
    float acc[4][4] = {};

    const int nbeg = chunk * (Nn / SPLITK);
    const int nld  = tid >> 4;               // 0..15
    const int cq   = (tid & 15) * 4;

    for (int n0 = nbeg; n0 < nbeg + Nn / SPLITK; n0 += 16) {
        *(float4*)&As[nld][cq] = *(const float4*)(Kp + (size_t)(n0 + nld) * Dd + d0 + cq);
        *(float4*)&Bs[nld][cq] = *(const float4*)(Vp + (size_t)(n0 + nld) * Dd + e0 + cq);
        __syncthreads();
#pragma unroll
        for (int kk = 0; kk < 16; kk++) {
            float4 ra = *(const float4*)&As[kk][ty*4];
            float4 rb = *(const float4*)&Bs[kk][tx*4];
            float a[4] = {ra.x, ra.y, ra.z, ra.w};
            float bb[4] = {rb.x, rb.y, rb.z, rb.w};
#pragma unroll
            for (int i = 0; i < 4; i++)
#pragma unroll
                for (int j = 0; j < 4; j++) acc[i][j] += a[i] * bb[j];
        }
        __syncthreads();
    }

    float* out = g_kv + (size_t)b * Dd * Dd;
#pragma unroll
    for (int i = 0; i < 4; i++)
#pragma unroll
        for (int j = 0; j < 4; j++)
            atomicAdd(&out[(size_t)(d0 + ty*4 + i) * Dd + e0 + tx*4 + j], acc[i][j]);
}

// ---------------------------------------------------------------------------
// out[b,m,e] = sum_d Q[b,m,d] * kv[b,d,e]   (64x64x16 tile)
// ---------------------------------------------------------------------------
__global__ __launch_bounds__(256) void out_gemm(float* __restrict__ out)
{
    __shared__ float As[16][64];
    __shared__ float Bs[16][64];
    const int tid = threadIdx.x;
    const int tx = tid & 15, ty = tid >> 4;
    const int b = blockIdx.z;
    const int m0 = blockIdx.y * 64;
    const int e0 = blockIdx.x * 64;
    const float* Qp = g_q + (size_t)b * Nn * Dd;
    const float* KVp = g_kv + (size_t)b * Dd * Dd;
    float acc[4][4] = {};

    const int mld = tid >> 2;                // 0..63
    const int kq  = (tid & 3) * 4;
    const int kr  = tid >> 4;                // 0..15
    const int eq  = (tid & 15) * 4;

    for (int k0 = 0; k0 < Dd; k0 += 16) {
        float4 a = *(const float4*)(Qp + (size_t)(m0 + mld) * Dd + k0 + kq);
        As[kq+0][mld] = a.x; As[kq+1][mld] = a.y; As[kq+2][mld] = a.z; As[kq+3][mld] = a.w;
        *(float4*)&Bs[kr][eq] = *(const float4*)(KVp + (size_t)(k0 + kr) * Dd + e0 + eq);
        __syncthreads();
#pragma unroll
        for (int kk = 0; kk < 16; kk++) {
            float4 ra = *(const float4*)&As[kk][ty*4];
            float4 rb = *(const float4*)&Bs[kk][tx*4];
            float a4[4] = {ra.x, ra.y, ra.z, ra.w};
            float b4[4] = {rb.x, rb.y, rb.z, rb.w};
#pragma unroll
            for (int i = 0; i < 4; i++)
#pragma unroll
                for (int j = 0; j < 4; j++) acc[i][j] += a4[i] * b4[j];
        }
        __syncthreads();
    }

#pragma unroll
    for (int i = 0; i < 4; i++) {
        int m = m0 + ty*4 + i;
        float4 o = {acc[i][0], acc[i][1], acc[i][2], acc[i][3]};
        *(float4*)(out + (size_t)(b * Nn + m) * Dd + e0 + tx*4) = o;
    }
}

// ---------------------------------------------------------------------------
extern "C" void kernel_launch(void* const* d_in, const int* in_sizes, int n_in,
                              void* d_out, int out_size)
{
    (void)in_sizes; (void)n_in; (void)out_size;
    const float* phi     = (const float*)d_in[0];
    const float* coords  = (const float*)d_in[1];
    const float* weights = (const float*)d_in[2];
    const float* Wq      = (const float*)d_in[3];
    const float* bq      = (const float*)d_in[4];
    const float* Wk      = (const float*)d_in[5];
    const float* bk      = (const float*)d_in[6];
    const float* Wv      = (const float*)d_in[7];
    const float* bv      = (const float*)d_in[8];
    const float* Wrot    = (const float*)d_in[9];
    float* out = (float*)d_out;

    float *q_ptr, *k_ptr, *v_ptr;
    cudaGetSymbolAddress((void**)&q_ptr, g_q);
    cudaGetSymbolAddress((void**)&k_ptr, g_k);
    cudaGetSymbolAddress((void**)&v_ptr, g_v);

    dim3 gqkv(Dd / 128, Mm / 128);       // (4, 256)
    gemm_nt128<<<gqkv, 256>>>(phi, Wq, bq, q_ptr);
    gemm_nt128<<<gqkv, 256>>>(phi, Wk, bk, k_ptr);
    gemm_nt128<<<gqkv, 256>>>(phi, Wv, bv, v_ptr);

    epilogue_rope<<<Mm, 256>>>(coords, weights, Wrot);

    zero_kv_kernel<<<(Bb * Dd * Dd) / 256, 256>>>();

    dim3 gkv(Dd / 64, Dd / 64, Bb * SPLITK);   // (8, 8, 32)
    kv_gemm<<<gkv, 256>>>();

    dim3 gout(Dd / 64, Nn / 64, Bb);           // (8, 64, 8)
    out_gemm<<<gout, 256>>>(out);
}

// round 2
// speedup vs baseline: 1.0020x; 1.0020x over previous
#include <cuda_runtime.h>
#include <math.h>

#define Bb 8
#define Nn 4096
#define Dd 512
#define Mm (Bb*Nn)    // 32768 rows
#define Hh (Dd/2)     // 256
#define SPLITK 4

// Scratch (allocation-free rule: __device__ globals)
__device__ float g_q[(size_t)Mm*Dd];
__device__ float g_k[(size_t)Mm*Dd];
__device__ float g_v[(size_t)Mm*Dd];
__device__ float g_kv[(size_t)Bb*Dd*Dd];

// ---------------------------------------------------------------------------
// C[M,512] = A[M,512] @ W[512,512]^T + bias   (128x128x16 tile, 8x8 per thread)
// ---------------------------------------------------------------------------
__global__ __launch_bounds__(256) void gemm_nt128(
    const float* __restrict__ A, const float* __restrict__ W,
    const float* __restrict__ bias, float* __restrict__ C)
{
    __shared__ float As[16][128];
    __shared__ float Bs[16][128];
    const int tid = threadIdx.x;
    const int tx = tid & 15, ty = tid >> 4;
    const int m0 = blockIdx.y * 128;
    const int n0 = blockIdx.x * 128;
    float acc[8][8] = {};

    for (int k0 = 0; k0 < Dd; k0 += 16) {
#pragma unroll
        for (int r = 0; r < 2; r++) {
            int e  = tid + r * 256;
            int m  = e >> 2;
            int kq = (e & 3) * 4;
            float4 a = *reinterpret_cast<const float4*>(A + (size_t)(m0 + m) * Dd + k0 + kq);
            As[kq+0][m] = a.x; As[kq+1][m] = a.y; As[kq+2][m] = a.z; As[kq+3][m] = a.w;
            float4 w = *reinterpret_cast<const float4*>(W + (size_t)(n0 + m) * Dd + k0 + kq);
            Bs[kq+0][m] = w.x; Bs[kq+1][m] = w.y; Bs[kq+2][m] = w.z; Bs[kq+3][m] = w.w;
        }
        __syncthreads();
#pragma unroll
        for (int kk = 0; kk < 16; kk++) {
            float a[8], b[8];
            *(float4*)&a[0] = *(const float4*)&As[kk][ty*8];
            *(float4*)&a[4] = *(const float4*)&As[kk][ty*8+4];
            *(float4*)&b[0] = *(const float4*)&Bs[kk][tx*8];
            *(float4*)&b[4] = *(const float4*)&Bs[kk][tx*8+4];
#pragma unroll
            for (int i = 0; i < 8; i++)
#pragma unroll
                for (int j = 0; j < 8; j++) acc[i][j] += a[i] * b[j];
        }
        __syncthreads();
    }

    float bcol[8];
#pragma unroll
    for (int j = 0; j < 8; j++) bcol[j] = bias[n0 + tx*8 + j];
#pragma unroll
    for (int i = 0; i < 8; i++) {
        int m = m0 + ty*8 + i;
        float4 o0, o1;
        o0.x = acc[i][0] + bcol[0]; o0.y = acc[i][1] + bcol[1];
        o0.z = acc[i][2] + bcol[2]; o0.w = acc[i][3] + bcol[3];
        o1.x = acc[i][4] + bcol[4]; o1.y = acc[i][5] + bcol[5];
        o1.z = acc[i][6] + bcol[6]; o1.w = acc[i][7] + bcol[7];
        *(float4*)(C + (size_t)m * Dd + n0 + tx*8)     = o0;
        *(float4*)(C + (size_t)m * Dd + n0 + tx*8 + 4) = o1;
    }
}

// ---------------------------------------------------------------------------
// Rotary + scaling epilogue. One block per row; thread i handles pair (i, i+256).
// ---------------------------------------------------------------------------
__global__ __launch_bounds__(256) void epilogue_rope(
    const float* __restrict__ coords, const float* __restrict__ weights,
    const float* __restrict__ Wrot)
{
    const int row = blockIdx.x;
    const int i = threadIdx.x;   // 0..255
    const float c0 = coords[row*3+0], c1 = coords[row*3+1], c2 = coords[row*3+2];
    const float p = c0*Wrot[i*3+0] + c1*Wrot[i*3+1] + c2*Wrot[i*3+2];
    float s, c;
    sincosf(p, &s, &c);
    const float scale = 0.04419417382415922f;   // 1/sqrt(512)
    const size_t base = (size_t)row * Dd;

    float qa = g_q[base + i], qb = g_q[base + i + Hh];
    g_q[base + i]      = (qa*c - qb*s) * scale;
    g_q[base + i + Hh] = (qa*s + qb*c) * scale;

    float ka = g_k[base + i], kb = g_k[base + i + Hh];
    g_k[base + i]      = ka*c - kb*s;
    g_k[base + i + Hh] = ka*s + kb*c;

    const float w = weights[row];
    g_v[base + i]      *= w;
    g_v[base + i + Hh] *= w;
}

// ---------------------------------------------------------------------------
__global__ __launch_bounds__(256) void zero_kv_kernel()
{
    size_t i = (size_t)blockIdx.x * 256 + threadIdx.x;
    g_kv[i] = 0.0f;
}

// ---------------------------------------------------------------------------
// kv[b,d,e] = sum_n K[b,n,d] * V[b,n,e]   (64x64x16 tile, split-K over n, atomicAdd)
// ---------------------------------------------------------------------------
__global__ __launch_bounds__(256) void kv_gemm()
{
    __shared__ float As[16][64];
    __shared__ float Bs[16][64];
    const int tid = threadIdx.x;
    const int tx = tid & 15, ty = tid >> 4;
    const int b = blockIdx.z >> 2;           // / SPLITK
    const int chunk = blockIdx.z & 3;
    const int d0 = blockIdx.y * 64;
    const int e0 = blockIdx.x * 64;
    const float* Kp = g_k + (size_t)b * Nn * Dd;
    const float* Vp = g_v + (size_t)b * Nn * Dd;
    float acc[4][4] = {};

    const int nbeg = chunk * (Nn / SPLITK);
    const int nld  = tid >> 4;               // 0..15
    const int cq   = (tid & 15) * 4;

    for (int n0 = nbeg; n0 < nbeg + Nn / SPLITK; n0 += 16) {
        *(float4*)&As[nld][cq] = *(const float4*)(Kp + (size_t)(n0 + nld) * Dd + d0 + cq);
        *(float4*)&Bs[nld][cq] = *(const float4*)(Vp + (size_t)(n0 + nld) * Dd + e0 + cq);
        __syncthreads();
#pragma unroll
        for (int kk = 0; kk < 16; kk++) {
            float4 ra = *(const float4*)&As[kk][ty*4];
            float4 rb = *(const float4*)&Bs[kk][tx*4];
            float a[4] = {ra.x, ra.y, ra.z, ra.w};
            float bb[4] = {rb.x, rb.y, rb.z, rb.w};
#pragma unroll
            for (int i = 0; i < 4; i++)
#pragma unroll
                for (int j = 0; j < 4; j++) acc[i][j] += a[i] * bb[j];
        }
        __syncthreads();
    }

    float* out = g_kv + (size_t)b * Dd * Dd;
#pragma unroll
    for (int i = 0; i < 4; i++)
#pragma unroll
        for (int j = 0; j < 4; j++)
            atomicAdd(&out[(size_t)(d0 + ty*4 + i) * Dd + e0 + tx*4 + j], acc[i][j]);
}

// ---------------------------------------------------------------------------
// out[b,m,e] = sum_d Q[b,m,d] * kv[b,d,e]   (64x64x16 tile)
// ---------------------------------------------------------------------------
__global__ __launch_bounds__(256) void out_gemm(float* __restrict__ out)
{
    __shared__ float As[16][64];
    __shared__ float Bs[16][64];
    const int tid = threadIdx.x;
    const int tx = tid & 15, ty = tid >> 4;
    const int b = blockIdx.z;
    const int m0 = blockIdx.y * 64;
    const int e0 = blockIdx.x * 64;
    const float* Qp = g_q + (size_t)b * Nn * Dd;
    const float* KVp = g_kv + (size_t)b * Dd * Dd;
    float acc[4][4] = {};

    const int mld = tid >> 2;                // 0..63
    const int kq  = (tid & 3) * 4;
    const int kr  = tid >> 4;                // 0..15
    const int eq  = (tid & 15) * 4;

    for (int k0 = 0; k0 < Dd; k0 += 16) {
        float4 a = *(const float4*)(Qp + (size_t)(m0 + mld) * Dd + k0 + kq);
        As[kq+0][mld] = a.x; As[kq+1][mld] = a.y; As[kq+2][mld] = a.z; As[kq+3][mld] = a.w;
        *(float4*)&Bs[kr][eq] = *(const float4*)(KVp + (size_t)(k0 + kr) * Dd + e0 + eq);
        __syncthreads();
#pragma unroll
        for (int kk = 0; kk < 16; kk++) {
            float4 ra = *(const float4*)&As[kk][ty*4];
            float4 rb = *(const float4*)&Bs[kk][tx*4];
            float a4[4] = {ra.x, ra.y, ra.z, ra.w};
            float b4[4] = {rb.x, rb.y, rb.z, rb.w};
#pragma unroll
            for (int i = 0; i < 4; i++)
#pragma unroll
                for (int j = 0; j < 4; j++) acc[i][j] += a4[i] * b4[j];
        }
        __syncthreads();
    }

#pragma unroll
    for (int i = 0; i < 4; i++) {
        int m = m0 + ty*4 + i;
        float4 o = {acc[i][0], acc[i][1], acc[i][2], acc[i][3]};
        *(float4*)(out + (size_t)(b * Nn + m) * Dd + e0 + tx*4) = o;
    }
}

// ---------------------------------------------------------------------------
extern "C" void kernel_launch(void* const* d_in, const int* in_sizes, int n_in,
                              void* d_out, int out_size)
{
    (void)in_sizes; (void)n_in; (void)out_size;
    const float* phi     = (const float*)d_in[0];
    const float* coords  = (const float*)d_in[1];
    const float* weights = (const float*)d_in[2];
    const float* Wq      = (const float*)d_in[3];
    const float* bq      = (const float*)d_in[4];
    const float* Wk      = (const float*)d_in[5];
    const float* bk      = (const float*)d_in[6];
    const float* Wv      = (const float*)d_in[7];
    const float* bv      = (const float*)d_in[8];
    const float* Wrot    = (const float*)d_in[9];
    float* out = (float*)d_out;

    float *q_ptr, *k_ptr, *v_ptr;
    cudaGetSymbolAddress((void**)&q_ptr, g_q);
    cudaGetSymbolAddress((void**)&k_ptr, g_k);
    cudaGetSymbolAddress((void**)&v_ptr, g_v);

    dim3 gqkv(Dd / 128, Mm / 128);       // (4, 256)
    gemm_nt128<<<gqkv, 256>>>(phi, Wq, bq, q_ptr);
    gemm_nt128<<<gqkv, 256>>>(phi, Wk, bk, k_ptr);
    gemm_nt128<<<gqkv, 256>>>(phi, Wv, bv, v_ptr);

    epilogue_rope<<<Mm, 256>>>(coords, weights, Wrot);

    zero_kv_kernel<<<(Bb * Dd * Dd) / 256, 256>>>();

    dim3 gkv(Dd / 64, Dd / 64, Bb * SPLITK);   // (8, 8, 32)
    kv_gemm<<<gkv, 256>>>();

    dim3 gout(Dd / 64, Nn / 64, Bb);           // (8, 64, 8)
    out_gemm<<<gout, 256>>>(out);
}

// round 4
// speedup vs baseline: 1.7495x; 1.7461x over previous
#include <cuda_runtime.h>
#include <cuda_bf16.h>
#include <math.h>
#include <stdint.h>

#define Bb 8
#define Nn 4096
#define Dd 512
#define Mm (Bb*Nn)      // 32768
#define QKVC 1536

// ---------------- scratch (__device__ globals; allocation-free rule) --------
__device__ __nv_bfloat16 g_phi_hi[(size_t)Mm*Dd];
__device__ __nv_bfloat16 g_phi_lo[(size_t)Mm*Dd];
__device__ __nv_bfloat16 g_W_hi[(size_t)QKVC*Dd];
__device__ __nv_bfloat16 g_W_lo[(size_t)QKVC*Dd];
__device__ float         g_bias[QKVC];
__device__ float         g_qkv[(size_t)Mm*QKVC];
__device__ __nv_bfloat16 g_q_hi[(size_t)Mm*Dd];
__device__ __nv_bfloat16 g_q_lo[(size_t)Mm*Dd];
__device__ __nv_bfloat16 g_kT_hi[(size_t)Bb*Dd*Nn];
__device__ __nv_bfloat16 g_kT_lo[(size_t)Bb*Dd*Nn];
__device__ __nv_bfloat16 g_vT_hi[(size_t)Bb*Dd*Nn];
__device__ __nv_bfloat16 g_vT_lo[(size_t)Bb*Dd*Nn];
__device__ __nv_bfloat16 g_kvT_hi[(size_t)Bb*Dd*Dd];
__device__ __nv_bfloat16 g_kvT_lo[(size_t)Bb*Dd*Dd];

// ---------------- helpers ----------------------------------------------------
__device__ __forceinline__ uint32_t smem_u32(const void* p) {
    uint32_t a;
    asm("{ .reg .u64 t; cvta.to.shared.u64 t, %1; cvt.u32.u64 %0, t; }" : "=r"(a) : "l"(p));
    return a;
}
__device__ __forceinline__ void cp16(uint32_t dst, const void* src) {
    asm volatile("cp.async.cg.shared.global [%0], [%1], 16;" :: "r"(dst), "l"(src) : "memory");
}
__device__ __forceinline__ void ldsm4(uint32_t* r, uint32_t addr) {
    asm volatile("ldmatrix.sync.aligned.m8n8.x4.shared.b16 {%0,%1,%2,%3}, [%4];"
                 : "=r"(r[0]), "=r"(r[1]), "=r"(r[2]), "=r"(r[3]) : "r"(addr));
}
__device__ __forceinline__ void mma16816(float* d, const uint32_t* a, const uint32_t* b) {
    asm volatile(
        "mma.sync.aligned.m16n8k16.row.col.f32.bf16.bf16.f32 "
        "{%0,%1,%2,%3}, {%4,%5,%6,%7}, {%8,%9}, {%0,%1,%2,%3};"
        : "+f"(d[0]), "+f"(d[1]), "+f"(d[2]), "+f"(d[3])
        : "r"(a[0]), "r"(a[1]), "r"(a[2]), "r"(a[3]), "r"(b[0]), "r"(b[1]));
}
__device__ __forceinline__ uint32_t packsplit(float v) {
    __nv_bfloat16 h = __float2bfloat16(v);
    __nv_bfloat16 l = __float2bfloat16(v - __bfloat162float(h));
    return (uint32_t)__bfloat16_as_ushort(h) | ((uint32_t)__bfloat16_as_ushort(l) << 16);
}

// ---------------------------------------------------------------------------
// Warp-MMA bf16 split GEMM: D[m,n] = sum_parts A_p[m,:] . B_p[n,:]
// parts: (Ahi,Bhi), (Alo,Bhi), (Ahi,Blo).  Block tile 128x128x32, 8 warps.
// EPI: 0 fp32 store, 1 fp32+bias, 2 bf16 hi/lo split store.
// smem rows padded to 80B: 8 consecutive row addrs hit distinct 16B segments
// mod 128B -> conflict-free ldmatrix without XOR swizzle.
// ---------------------------------------------------------------------------
#define RB 80          // row stride bytes (32 bf16 = 64B data + 16B pad)
#define STG (128*RB)   // 10240 bytes per operand stage

template<int EPI>
__global__ __launch_bounds__(256) void mma_gemm(
    const __nv_bfloat16* __restrict__ Ahi, const __nv_bfloat16* __restrict__ Alo,
    const __nv_bfloat16* __restrict__ Bhi, const __nv_bfloat16* __restrict__ Blo,
    int Kdim, size_t aBS, size_t bBS,
    float* __restrict__ C, size_t cBS, int ldc,
    const float* __restrict__ bias,
    __nv_bfloat16* __restrict__ Chi, __nv_bfloat16* __restrict__ Clo, size_t cbBS)
{
    __shared__ __align__(16) char smem[2 * 2 * STG];   // [stage][A|B]
    const uint32_t sbase = smem_u32(smem);
    const int tid  = threadIdx.x;
    const int lane = tid & 31;
    const int wid  = tid >> 5;
    const int wm   = wid >> 2;          // 0..1 (64 rows each)
    const int wn   = wid & 3;           // 0..3 (32 cols each)
    const int n0 = blockIdx.x * 128;
    const int m0 = blockIdx.y * 128;
    const int bz = blockIdx.z;

    const int KS = Kdim >> 5;           // k-chunks of 32 per part
    const int S  = 3 * KS;
    const __nv_bfloat16* Ap[2] = { Ahi + (size_t)bz * aBS, Alo + (size_t)bz * aBS };
    const __nv_bfloat16* Bp[2] = { Bhi + (size_t)bz * bBS, Blo + (size_t)bz * bBS };

    // loader: 256 threads, each 2x16B for A and B
    const int lr = tid >> 1;            // row 0..127
    const int lc = (tid & 1) * 2;       // chunk 0 or 2

    auto load = [&](int s) {
        int part = s / KS;
        int k0 = (s - part * KS) << 5;
        const __nv_bfloat16* A = Ap[part == 1];
        const __nv_bfloat16* B = Bp[part == 2];
        uint32_t sa = sbase + (s & 1) * 2 * STG;
        uint32_t sbB = sa + STG;
        const __nv_bfloat16* ag = A + (size_t)(m0 + lr) * Kdim + k0 + lc * 8;
        cp16(sa + lr * RB + lc * 16, ag);
        cp16(sa + lr * RB + lc * 16 + 16, ag + 8);
        const __nv_bfloat16* bg = B + (size_t)(n0 + lr) * Kdim + k0 + lc * 8;
        cp16(sbB + lr * RB + lc * 16, bg);
        cp16(sbB + lr * RB + lc * 16 + 16, bg + 8);
        asm volatile("cp.async.commit_group;" ::: "memory");
    };

    // ldmatrix per-lane byte offsets
    const uint32_t laA = ((lane & 7) + ((lane >> 3) & 1) * 8) * RB + (lane >> 4) * 16;
    const uint32_t laB = ((lane & 7) + (lane >> 4) * 8) * RB + ((lane >> 3) & 1) * 16;

    float acc[4][4][4] = {};

    load(0); load(1);

    for (int s = 0; s < S; s++) {
        if (s + 1 < S) asm volatile("cp.async.wait_group 1;" ::: "memory");
        else           asm volatile("cp.async.wait_group 0;" ::: "memory");
        __syncthreads();
        uint32_t sa  = sbase + (s & 1) * 2 * STG;
        uint32_t sbB = sa + STG;
#pragma unroll
        for (int ks = 0; ks < 2; ks++) {
            uint32_t a[4][4], b[2][4];
#pragma unroll
            for (int mf = 0; mf < 4; mf++)
                ldsm4(a[mf], sa + (wm * 64 + mf * 16) * RB + ks * 32 + laA);
#pragma unroll
            for (int bp = 0; bp < 2; bp++)
                ldsm4(b[bp], sbB + (wn * 32 + bp * 16) * RB + ks * 32 + laB);
#pragma unroll
            for (int mf = 0; mf < 4; mf++)
#pragma unroll
                for (int nf = 0; nf < 4; nf++)
                    mma16816(acc[mf][nf], a[mf], &b[nf >> 1][(nf & 1) * 2]);
        }
        __syncthreads();
        if (s + 2 < S) load(s + 2);
    }

    // epilogue
    const int g = lane >> 2;
    const int cq = (lane & 3) * 2;
#pragma unroll
    for (int mf = 0; mf < 4; mf++) {
#pragma unroll
        for (int nf = 0; nf < 4; nf++) {
            int row = m0 + wm * 64 + mf * 16 + g;
            int col = n0 + wn * 32 + nf * 8 + cq;
            float c0 = acc[mf][nf][0], c1 = acc[mf][nf][1];
            float c2 = acc[mf][nf][2], c3 = acc[mf][nf][3];
            if constexpr (EPI == 0) {
                float* dst = C + (size_t)bz * cBS + (size_t)row * ldc + col;
                *(float2*)dst = make_float2(c0, c1);
                *(float2*)(dst + 8 * ldc) = make_float2(c2, c3);
            } else if constexpr (EPI == 1) {
                float b0 = bias[col], b1 = bias[col + 1];
                float* dst = C + (size_t)bz * cBS + (size_t)row * ldc + col;
                *(float2*)dst = make_float2(c0 + b0, c1 + b1);
                *(float2*)(dst + 8 * ldc) = make_float2(c2 + b0, c3 + b1);
            } else {
                size_t off = (size_t)bz * cbBS + (size_t)row * ldc + col;
                uint32_t p0 = packsplit(c0), p1 = packsplit(c1);
                *(uint32_t*)(Chi + off) = (p0 & 0xffffu) | (p1 << 16);
                *(uint32_t*)(Clo + off) = (p0 >> 16) | (p1 & 0xffff0000u);
                uint32_t p2 = packsplit(c2), p3 = packsplit(c3);
                *(uint32_t*)(Chi + off + 8 * ldc) = (p2 & 0xffffu) | (p3 << 16);
                *(uint32_t*)(Clo + off + 8 * ldc) = (p2 >> 16) | (p3 & 0xffff0000u);
            }
        }
    }
}

// ---------------------------------------------------------------------------
__global__ __launch_bounds__(256) void pack_phi(const float* __restrict__ phi)
{
    size_t i = ((size_t)blockIdx.x * 256 + threadIdx.x) * 4;
    float4 x = *(const float4*)(phi + i);
    uint32_t a = packsplit(x.x), b = packsplit(x.y), c = packsplit(x.z), d = packsplit(x.w);
    *(uint32_t*)(g_phi_hi + i)     = (a & 0xffffu) | (b << 16);
    *(uint32_t*)(g_phi_hi + i + 2) = (c & 0xffffu) | (d << 16);
    *(uint32_t*)(g_phi_lo + i)     = (a >> 16) | (b & 0xffff0000u);
    *(uint32_t*)(g_phi_lo + i + 2) = (c >> 16) | (d & 0xffff0000u);
}

__global__ __launch_bounds__(128) void pack_W(
    const float* __restrict__ Wq, const float* __restrict__ bq,
    const float* __restrict__ Wk, const float* __restrict__ bk,
    const float* __restrict__ Wv, const float* __restrict__ bv)
{
    int r = blockIdx.x, t = threadIdx.x;
    const float* src; const float* bs; int sr;
    if (r < 512)       { src = Wq; bs = bq; sr = r; }
    else if (r < 1024) { src = Wk; bs = bk; sr = r - 512; }
    else               { src = Wv; bs = bv; sr = r - 1024; }
    float4 x = *(const float4*)(src + (size_t)sr * Dd + t * 4);
    size_t o = (size_t)r * Dd + t * 4;
    uint32_t a = packsplit(x.x), b = packsplit(x.y), c = packsplit(x.z), d = packsplit(x.w);
    *(uint32_t*)(g_W_hi + o)     = (a & 0xffffu) | (b << 16);
    *(uint32_t*)(g_W_hi + o + 2) = (c & 0xffffu) | (d << 16);
    *(uint32_t*)(g_W_lo + o)     = (a >> 16) | (b & 0xffff0000u);
    *(uint32_t*)(g_W_lo + o + 2) = (c >> 16) | (d & 0xffff0000u);
    if (t == 0) g_bias[r] = bs[sr];
}

// ---------------------------------------------------------------------------
// RoPE + scale + weights + bf16 split; q row-major, k/v transposed to [b,d,n].
// grid: (Mm/32, 4) ; block 256.
// ---------------------------------------------------------------------------
__global__ __launch_bounds__(256) void rope_split(
    const float* __restrict__ coords, const float* __restrict__ weights,
    const float* __restrict__ Wrot)
{
    __shared__ float wr[64][3];
    __shared__ uint32_t sk[128][33];
    __shared__ uint32_t sv[128][33];
    const int t = threadIdx.x;
    const int d0 = blockIdx.y * 64;
    const int row0 = blockIdx.x * 32;
    if (t < 192) wr[t / 3][t % 3] = Wrot[(size_t)(d0 + t / 3) * 3 + (t % 3)];
    __syncthreads();

    const int r  = t >> 3;
    const int c0 = (t & 7) * 8;
    const int row = row0 + r;
    const float x0 = coords[row * 3 + 0], x1 = coords[row * 3 + 1], x2 = coords[row * 3 + 2];
    const float wgt = weights[row];
    const float scale = 0.04419417382415922f;   // 1/sqrt(512)
    const float* src = g_qkv + (size_t)row * QKVC;

    float q0v[8], q1v[8];
#pragma unroll
    for (int j = 0; j < 8; j++) {
        int h = d0 + c0 + j;
        float ph = x0 * wr[c0 + j][0] + x1 * wr[c0 + j][1] + x2 * wr[c0 + j][2];
        float s, c;
        sincosf(ph, &s, &c);
        float qa = src[h], qb = src[h + 256];
        q0v[j] = (qa * c - qb * s) * scale;
        q1v[j] = (qa * s + qb * c) * scale;
        float ka = src[512 + h], kb = src[512 + h + 256];
        sk[c0 + j][r]      = packsplit(ka * c - kb * s);
        sk[64 + c0 + j][r] = packsplit(ka * s + kb * c);
        sv[c0 + j][r]      = packsplit(src[1024 + h] * wgt);
        sv[64 + c0 + j][r] = packsplit(src[1024 + h + 256] * wgt);
    }
    uint32_t ph0[4], pl0[4], ph1[4], pl1[4];
#pragma unroll
    for (int j = 0; j < 4; j++) {
        uint32_t a = packsplit(q0v[2 * j]), b = packsplit(q0v[2 * j + 1]);
        ph0[j] = (a & 0xffffu) | (b << 16);
        pl0[j] = (a >> 16) | (b & 0xffff0000u);
        uint32_t c = packsplit(q1v[2 * j]), d = packsplit(q1v[2 * j + 1]);
        ph1[j] = (c & 0xffffu) | (d << 16);
        pl1[j] = (c >> 16) | (d & 0xffff0000u);
    }
    size_t qo = (size_t)row * Dd + d0 + c0;
    *(uint4*)(g_q_hi + qo)       = *(uint4*)ph0;
    *(uint4*)(g_q_lo + qo)       = *(uint4*)pl0;
    *(uint4*)(g_q_hi + qo + 256) = *(uint4*)ph1;
    *(uint4*)(g_q_lo + qo + 256) = *(uint4*)pl1;

    __syncthreads();
    const int b   = row0 / Nn;
    const int nn0 = row0 % Nn;
    const int dl  = t >> 1;
    const int j0  = (t & 1) * 16;
    const int dmap = (dl < 64) ? d0 + dl : d0 + 256 + (dl - 64);
    size_t off = ((size_t)b * Dd + dmap) * Nn + nn0 + j0;
    uint32_t hb[8], lb[8];
#pragma unroll
    for (int j = 0; j < 8; j++) {
        uint32_t a = sk[dl][j0 + 2 * j], c = sk[dl][j0 + 2 * j + 1];
        hb[j] = (a & 0xffffu) | (c << 16);
        lb[j] = (a >> 16) | (c & 0xffff0000u);
    }
    *(uint4*)(g_kT_hi + off)     = *(uint4*)hb;
    *(uint4*)(g_kT_hi + off + 8) = *(uint4*)(hb + 4);
    *(uint4*)(g_kT_lo + off)     = *(uint4*)lb;
    *(uint4*)(g_kT_lo + off + 8) = *(uint4*)(lb + 4);
#pragma unroll
    for (int j = 0; j < 8; j++) {
        uint32_t a = sv[dl][j0 + 2 * j], c = sv[dl][j0 + 2 * j + 1];
        hb[j] = (a & 0xffffu) | (c << 16);
        lb[j] = (a >> 16) | (c & 0xffff0000u);
    }
    *(uint4*)(g_vT_hi + off)     = *(uint4*)hb;
    *(uint4*)(g_vT_hi + off + 8) = *(uint4*)(hb + 4);
    *(uint4*)(g_vT_lo + off)     = *(uint4*)lb;
    *(uint4*)(g_vT_lo + off + 8) = *(uint4*)(lb + 4);
}

// ---------------------------------------------------------------------------
extern "C" void kernel_launch(void* const* d_in, const int* in_sizes, int n_in,
                              void* d_out, int out_size)
{
    (void)in_sizes; (void)n_in; (void)out_size;
    const float* phi     = (const float*)d_in[0];
    const float* coords  = (const float*)d_in[1];
    const float* weights = (const float*)d_in[2];
    const float* Wq      = (const float*)d_in[3];
    const float* bq      = (const float*)d_in[4];
    const float* Wk      = (const float*)d_in[5];
    const float* bk      = (const float*)d_in[6];
    const float* Wv      = (const float*)d_in[7];
    const float* bv      = (const float*)d_in[8];
    const float* Wrot    = (const float*)d_in[9];
    float* out = (float*)d_out;

    __nv_bfloat16 *phi_hi, *phi_lo, *W_hi, *W_lo, *q_hi, *q_lo;
    __nv_bfloat16 *kT_hi, *kT_lo, *vT_hi, *vT_lo, *kvT_hi, *kvT_lo;
    float *qkv, *bias;
    cudaGetSymbolAddress((void**)&phi_hi, g_phi_hi);
    cudaGetSymbolAddress((void**)&phi_lo, g_phi_lo);
    cudaGetSymbolAddress((void**)&W_hi,   g_W_hi);
    cudaGetSymbolAddress((void**)&W_lo,   g_W_lo);
    cudaGetSymbolAddress((void**)&q_hi,   g_q_hi);
    cudaGetSymbolAddress((void**)&q_lo,   g_q_lo);
    cudaGetSymbolAddress((void**)&kT_hi,  g_kT_hi);
    cudaGetSymbolAddress((void**)&kT_lo,  g_kT_lo);
    cudaGetSymbolAddress((void**)&vT_hi,  g_vT_hi);
    cudaGetSymbolAddress((void**)&vT_lo,  g_vT_lo);
    cudaGetSymbolAddress((void**)&kvT_hi, g_kvT_hi);
    cudaGetSymbolAddress((void**)&kvT_lo, g_kvT_lo);
    cudaGetSymbolAddress((void**)&qkv,    g_qkv);
    cudaGetSymbolAddress((void**)&bias,   g_bias);

    pack_phi<<<(Mm * Dd) / 1024, 256>>>(phi);
    pack_W<<<QKVC, 128>>>(Wq, bq, Wk, bk, Wv, bv);

    // qkv = phi @ Wcat^T + bias
    mma_gemm<1><<<dim3(QKVC/128, Mm/128, 1), 256>>>(
        phi_hi, phi_lo, W_hi, W_lo, Dd, 0, 0,
        qkv, 0, QKVC, bias, nullptr, nullptr, 0);

    rope_split<<<dim3(Mm/32, 4), 256>>>(coords, weights, Wrot);

    // kvT[e,d] = sum_n vT[e,n]*kT[d,n]   (bf16 hi/lo out)
    mma_gemm<2><<<dim3(Dd/128, Dd/128, Bb), 256>>>(
        vT_hi, vT_lo, kT_hi, kT_lo, Nn, (size_t)Dd*Nn, (size_t)Dd*Nn,
        nullptr, 0, Dd, nullptr, kvT_hi, kvT_lo, (size_t)Dd*Dd);

    // out[m,e] = sum_d q[m,d]*kvT[e,d]
    mma_gemm<0><<<dim3(Dd/128, Nn/128, Bb), 256>>>(
        q_hi, q_lo, kvT_hi, kvT_lo, Dd, (size_t)Nn*Dd, (size_t)Dd*Dd,
        out, (size_t)Nn*Dd, Dd, nullptr, nullptr, nullptr, 0);
}

// round 5
// speedup vs baseline: 1.8669x; 1.0671x over previous
#include <cuda_runtime.h>
#include <cuda_bf16.h>
#include <math.h>
#include <stdint.h>

#define Bb 8
#define Nn 4096
#define Dd 512
#define Mm (Bb*Nn)      // 32768
#define QKVC 1536

// ---------------- scratch (__device__ globals; allocation-free rule) --------
__device__ __nv_bfloat16 g_phi_hi[(size_t)Mm*Dd];
__device__ __nv_bfloat16 g_phi_lo[(size_t)Mm*Dd];
__device__ __nv_bfloat16 g_W_hi[(size_t)QKVC*Dd];
__device__ __nv_bfloat16 g_W_lo[(size_t)QKVC*Dd];
__device__ float         g_bias[QKVC];
__device__ float         g_qkv[(size_t)Mm*QKVC];
__device__ __nv_bfloat16 g_q_hi[(size_t)Mm*Dd];
__device__ __nv_bfloat16 g_q_lo[(size_t)Mm*Dd];
__device__ __nv_bfloat16 g_kT_hi[(size_t)Bb*Dd*Nn];
__device__ __nv_bfloat16 g_kT_lo[(size_t)Bb*Dd*Nn];
__device__ __nv_bfloat16 g_vT_hi[(size_t)Bb*Dd*Nn];
__device__ __nv_bfloat16 g_vT_lo[(size_t)Bb*Dd*Nn];
__device__ __nv_bfloat16 g_kvT_hi[(size_t)Bb*Dd*Dd];
__device__ __nv_bfloat16 g_kvT_lo[(size_t)Bb*Dd*Dd];

// ---------------- helpers ----------------------------------------------------
__device__ __forceinline__ uint32_t smem_u32(const void* p) {
    uint32_t a;
    asm("{ .reg .u64 t; cvta.to.shared.u64 t, %1; cvt.u32.u64 %0, t; }" : "=r"(a) : "l"(p));
    return a;
}
__device__ __forceinline__ void cp16(uint32_t dst, const void* src) {
    asm volatile("cp.async.cg.shared.global [%0], [%1], 16;" :: "r"(dst), "l"(src) : "memory");
}
__device__ __forceinline__ void ldsm4(uint32_t* r, uint32_t addr) {
    asm volatile("ldmatrix.sync.aligned.m8n8.x4.shared.b16 {%0,%1,%2,%3}, [%4];"
                 : "=r"(r[0]), "=r"(r[1]), "=r"(r[2]), "=r"(r[3]) : "r"(addr));
}
__device__ __forceinline__ void mma16816(float* d, const uint32_t* a, const uint32_t* b) {
    asm volatile(
        "mma.sync.aligned.m16n8k16.row.col.f32.bf16.bf16.f32 "
        "{%0,%1,%2,%3}, {%4,%5,%6,%7}, {%8,%9}, {%0,%1,%2,%3};"
        : "+f"(d[0]), "+f"(d[1]), "+f"(d[2]), "+f"(d[3])
        : "r"(a[0]), "r"(a[1]), "r"(a[2]), "r"(a[3]), "r"(b[0]), "r"(b[1]));
}
__device__ __forceinline__ uint32_t packsplit(float v) {
    __nv_bfloat16 h = __float2bfloat16(v);
    __nv_bfloat16 l = __float2bfloat16(v - __bfloat162float(h));
    return (uint32_t)__bfloat16_as_ushort(h) | ((uint32_t)__bfloat16_as_ushort(l) << 16);
}

// ---------------------------------------------------------------------------
// Warp-MMA bf16 split GEMM: D[m,n] = sum_parts A_p[m,:] . B_p[n,:]
// parts: (Ahi,Bhi), (Alo,Bhi), (Ahi,Blo).  Block tile 128x128x32, 8 warps.
// 4-stage cp.async ring, ONE __syncthreads per k-step, loads issued pre-compute.
// smem rows padded to 80B -> conflict-free ldmatrix without XOR swizzle.
// EPI: 0 fp32 store, 1 fp32+bias, 2 bf16 hi/lo split store.
// ---------------------------------------------------------------------------
#define RB 80            // row stride bytes (32 bf16 = 64B data + 16B pad)
#define STG (128*RB)     // 10240 B per operand stage
#define SLOT (2*STG)     // A+B per stage
#define SMEMTOT (4*SLOT) // 81920 B

template<int EPI>
__global__ __launch_bounds__(256, 2) void mma_gemm(
    const __nv_bfloat16* __restrict__ Ahi, const __nv_bfloat16* __restrict__ Alo,
    const __nv_bfloat16* __restrict__ Bhi, const __nv_bfloat16* __restrict__ Blo,
    int Kdim, size_t aBS, size_t bBS,
    float* __restrict__ C, size_t cBS, int ldc,
    const float* __restrict__ bias,
    __nv_bfloat16* __restrict__ Chi, __nv_bfloat16* __restrict__ Clo, size_t cbBS)
{
    extern __shared__ __align__(16) char smem[];
    const uint32_t sbase = smem_u32(smem);
    const int tid  = threadIdx.x;
    const int lane = tid & 31;
    const int wid  = tid >> 5;
    const int wm   = wid >> 2;          // 0..1 (64 rows)
    const int wn   = wid & 3;           // 0..3 (32 cols)
    const int n0 = blockIdx.x * 128;
    const int m0 = blockIdx.y * 128;
    const int bz = blockIdx.z;

    const int KS = Kdim >> 5;           // 32-deep k-chunks per part
    const int S  = 3 * KS;
    const __nv_bfloat16* Ap[2] = { Ahi + (size_t)bz * aBS, Alo + (size_t)bz * aBS };
    const __nv_bfloat16* Bp[2] = { Bhi + (size_t)bz * bBS, Blo + (size_t)bz * bBS };

    const int lr = tid >> 1;            // loader row 0..127
    const int lc = (tid & 1) * 2;       // 16B chunk 0 or 2

    auto load = [&](int s) {
        int part = s / KS;
        int k0 = (s - part * KS) << 5;
        const __nv_bfloat16* A = Ap[part == 1];
        const __nv_bfloat16* B = Bp[part == 2];
        uint32_t da = sbase + (s & 3) * SLOT;
        uint32_t db = da + STG;
        const __nv_bfloat16* ag = A + (size_t)(m0 + lr) * Kdim + k0 + lc * 8;
        cp16(da + lr * RB + lc * 16, ag);
        cp16(da + lr * RB + lc * 16 + 16, ag + 8);
        const __nv_bfloat16* bg = B + (size_t)(n0 + lr) * Kdim + k0 + lc * 8;
        cp16(db + lr * RB + lc * 16, bg);
        cp16(db + lr * RB + lc * 16 + 16, bg + 8);
        asm volatile("cp.async.commit_group;" ::: "memory");
    };

    const uint32_t laA = ((lane & 7) + ((lane >> 3) & 1) * 8) * RB + (lane >> 4) * 16;
    const uint32_t laB = ((lane & 7) + (lane >> 4) * 8) * RB + ((lane >> 3) & 1) * 16;

    float acc[4][4][4] = {};

    load(0); load(1); load(2);

    for (int s = 0; s < S; s++) {
        asm volatile("cp.async.wait_group 2;" ::: "memory");
        __syncthreads();
        if (s + 3 < S) load(s + 3);     // slot (s-1)&3: consumed, post-sync safe
        uint32_t sa  = sbase + (s & 3) * SLOT;
        uint32_t sbB = sa + STG;
#pragma unroll
        for (int ks = 0; ks < 2; ks++) {
            uint32_t a[4][4], b[2][4];
#pragma unroll
            for (int mf = 0; mf < 4; mf++)
                ldsm4(a[mf], sa + (wm * 64 + mf * 16) * RB + ks * 32 + laA);
#pragma unroll
            for (int bp = 0; bp < 2; bp++)
                ldsm4(b[bp], sbB + (wn * 32 + bp * 16) * RB + ks * 32 + laB);
#pragma unroll
            for (int mf = 0; mf < 4; mf++)
#pragma unroll
                for (int nf = 0; nf < 4; nf++)
                    mma16816(acc[mf][nf], a[mf], &b[nf >> 1][(nf & 1) * 2]);
        }
    }

    // epilogue
    const int g = lane >> 2;
    const int cq = (lane & 3) * 2;
#pragma unroll
    for (int mf = 0; mf < 4; mf++) {
#pragma unroll
        for (int nf = 0; nf < 4; nf++) {
            int row = m0 + wm * 64 + mf * 16 + g;
            int col = n0 + wn * 32 + nf * 8 + cq;
            float c0 = acc[mf][nf][0], c1 = acc[mf][nf][1];
            float c2 = acc[mf][nf][2], c3 = acc[mf][nf][3];
            if constexpr (EPI == 0) {
                float* dst = C + (size_t)bz * cBS + (size_t)row * ldc + col;
                *(float2*)dst = make_float2(c0, c1);
                *(float2*)(dst + 8 * ldc) = make_float2(c2, c3);
            } else if constexpr (EPI == 1) {
                float b0 = __ldg(bias + col), b1 = __ldg(bias + col + 1);
                float* dst = C + (size_t)bz * cBS + (size_t)row * ldc + col;
                *(float2*)dst = make_float2(c0 + b0, c1 + b1);
                *(float2*)(dst + 8 * ldc) = make_float2(c2 + b0, c3 + b1);
            } else {
                size_t off = (size_t)bz * cbBS + (size_t)row * ldc + col;
                uint32_t p0 = packsplit(c0), p1 = packsplit(c1);
                *(uint32_t*)(Chi + off) = (p0 & 0xffffu) | (p1 << 16);
                *(uint32_t*)(Clo + off) = (p0 >> 16) | (p1 & 0xffff0000u);
                uint32_t p2 = packsplit(c2), p3 = packsplit(c3);
                *(uint32_t*)(Chi + off + 8 * ldc) = (p2 & 0xffffu) | (p3 << 16);
                *(uint32_t*)(Clo + off + 8 * ldc) = (p2 >> 16) | (p3 & 0xffff0000u);
            }
        }
    }
}

// ---------------------------------------------------------------------------
__global__ __launch_bounds__(256) void pack_phi(const float* __restrict__ phi)
{
    size_t i = ((size_t)blockIdx.x * 256 + threadIdx.x) * 4;
    float4 x = *(const float4*)(phi + i);
    uint32_t a = packsplit(x.x), b = packsplit(x.y), c = packsplit(x.z), d = packsplit(x.w);
    *(uint32_t*)(g_phi_hi + i)     = (a & 0xffffu) | (b << 16);
    *(uint32_t*)(g_phi_hi + i + 2) = (c & 0xffffu) | (d << 16);
    *(uint32_t*)(g_phi_lo + i)     = (a >> 16) | (b & 0xffff0000u);
    *(uint32_t*)(g_phi_lo + i + 2) = (c >> 16) | (d & 0xffff0000u);
}

__global__ __launch_bounds__(128) void pack_W(
    const float* __restrict__ Wq, const float* __restrict__ bq,
    const float* __restrict__ Wk, const float* __restrict__ bk,
    const float* __restrict__ Wv, const float* __restrict__ bv)
{
    int r = blockIdx.x, t = threadIdx.x;
    const float* src; const float* bs; int sr;
    if (r < 512)       { src = Wq; bs = bq; sr = r; }
    else if (r < 1024) { src = Wk; bs = bk; sr = r - 512; }
    else               { src = Wv; bs = bv; sr = r - 1024; }
    float4 x = *(const float4*)(src + (size_t)sr * Dd + t * 4);
    size_t o = (size_t)r * Dd + t * 4;
    uint32_t a = packsplit(x.x), b = packsplit(x.y), c = packsplit(x.z), d = packsplit(x.w);
    *(uint32_t*)(g_W_hi + o)     = (a & 0xffffu) | (b << 16);
    *(uint32_t*)(g_W_hi + o + 2) = (c & 0xffffu) | (d << 16);
    *(uint32_t*)(g_W_lo + o)     = (a >> 16) | (b & 0xffff0000u);
    *(uint32_t*)(g_W_lo + o + 2) = (c >> 16) | (d & 0xffff0000u);
    if (t == 0) g_bias[r] = bs[sr];
}

// ---------------------------------------------------------------------------
// RoPE + scale + weights + bf16 split; q row-major, k/v transposed to [b,d,n].
// grid: (Mm/32, 4) ; block 256.
// ---------------------------------------------------------------------------
__global__ __launch_bounds__(256) void rope_split(
    const float* __restrict__ coords, const float* __restrict__ weights,
    const float* __restrict__ Wrot)
{
    __shared__ float wr[64][3];
    __shared__ uint32_t sk[128][33];
    __shared__ uint32_t sv[128][33];
    const int t = threadIdx.x;
    const int d0 = blockIdx.y * 64;
    const int row0 = blockIdx.x * 32;
    if (t < 192) wr[t / 3][t % 3] = Wrot[(size_t)(d0 + t / 3) * 3 + (t % 3)];
    __syncthreads();

    const int r  = t >> 3;
    const int c0 = (t & 7) * 8;
    const int row = row0 + r;
    const float x0 = coords[row * 3 + 0], x1 = coords[row * 3 + 1], x2 = coords[row * 3 + 2];
    const float wgt = weights[row];
    const float scale = 0.04419417382415922f;   // 1/sqrt(512)
    const float* src = g_qkv + (size_t)row * QKVC;

    float q0v[8], q1v[8];
#pragma unroll
    for (int j = 0; j < 8; j++) {
        int h = d0 + c0 + j;
        float ph = x0 * wr[c0 + j][0] + x1 * wr[c0 + j][1] + x2 * wr[c0 + j][2];
        float s, c;
        __sincosf(ph, &s, &c);
        float qa = src[h], qb = src[h + 256];
        q0v[j] = (qa * c - qb * s) * scale;
        q1v[j] = (qa * s + qb * c) * scale;
        float ka = src[512 + h], kb = src[512 + h + 256];
        sk[c0 + j][r]      = packsplit(ka * c - kb * s);
        sk[64 + c0 + j][r] = packsplit(ka * s + kb * c);
        sv[c0 + j][r]      = packsplit(src[1024 + h] * wgt);
        sv[64 + c0 + j][r] = packsplit(src[1024 + h + 256] * wgt);
    }
    uint32_t ph0[4], pl0[4], ph1[4], pl1[4];
#pragma unroll
    for (int j = 0; j < 4; j++) {
        uint32_t a = packsplit(q0v[2 * j]), b = packsplit(q0v[2 * j + 1]);
        ph0[j] = (a & 0xffffu) | (b << 16);
        pl0[j] = (a >> 16) | (b & 0xffff0000u);
        uint32_t c = packsplit(q1v[2 * j]), d = packsplit(q1v[2 * j + 1]);
        ph1[j] = (c & 0xffffu) | (d << 16);
        pl1[j] = (c >> 16) | (d & 0xffff0000u);
    }
    size_t qo = (size_t)row * Dd + d0 + c0;
    *(uint4*)(g_q_hi + qo)       = *(uint4*)ph0;
    *(uint4*)(g_q_lo + qo)       = *(uint4*)pl0;
    *(uint4*)(g_q_hi + qo + 256) = *(uint4*)ph1;
    *(uint4*)(g_q_lo + qo + 256) = *(uint4*)pl1;

    __syncthreads();
    const int b   = row0 / Nn;
    const int nn0 = row0 % Nn;
    const int dl  = t >> 1;
    const int j0  = (t & 1) * 16;
    const int dmap = (dl < 64) ? d0 + dl : d0 + 256 + (dl - 64);
    size_t off = ((size_t)b * Dd + dmap) * Nn + nn0 + j0;
    uint32_t hb[8], lb[8];
#pragma unroll
    for (int j = 0; j < 8; j++) {
        uint32_t a = sk[dl][j0 + 2 * j], c = sk[dl][j0 + 2 * j + 1];
        hb[j] = (a & 0xffffu) | (c << 16);
        lb[j] = (a >> 16) | (c & 0xffff0000u);
    }
    *(uint4*)(g_kT_hi + off)     = *(uint4*)hb;
    *(uint4*)(g_kT_hi + off + 8) = *(uint4*)(hb + 4);
    *(uint4*)(g_kT_lo + off)     = *(uint4*)lb;
    *(uint4*)(g_kT_lo + off + 8) = *(uint4*)(lb + 4);
#pragma unroll
    for (int j = 0; j < 8; j++) {
        uint32_t a = sv[dl][j0 + 2 * j], c = sv[dl][j0 + 2 * j + 1];
        hb[j] = (a & 0xffffu) | (c << 16);
        lb[j] = (a >> 16) | (c & 0xffff0000u);
    }
    *(uint4*)(g_vT_hi + off)     = *(uint4*)hb;
    *(uint4*)(g_vT_hi + off + 8) = *(uint4*)(hb + 4);
    *(uint4*)(g_vT_lo + off)     = *(uint4*)lb;
    *(uint4*)(g_vT_lo + off + 8) = *(uint4*)(lb + 4);
}

// ---------------------------------------------------------------------------
extern "C" void kernel_launch(void* const* d_in, const int* in_sizes, int n_in,
                              void* d_out, int out_size)
{
    (void)in_sizes; (void)n_in; (void)out_size;
    const float* phi     = (const float*)d_in[0];
    const float* coords  = (const float*)d_in[1];
    const float* weights = (const float*)d_in[2];
    const float* Wq      = (const float*)d_in[3];
    const float* bq      = (const float*)d_in[4];
    const float* Wk      = (const float*)d_in[5];
    const float* bk      = (const float*)d_in[6];
    const float* Wv      = (const float*)d_in[7];
    const float* bv      = (const float*)d_in[8];
    const float* Wrot    = (const float*)d_in[9];
    float* out = (float*)d_out;

    cudaFuncSetAttribute(mma_gemm<0>, cudaFuncAttributeMaxDynamicSharedMemorySize, SMEMTOT);
    cudaFuncSetAttribute(mma_gemm<1>, cudaFuncAttributeMaxDynamicSharedMemorySize, SMEMTOT);
    cudaFuncSetAttribute(mma_gemm<2>, cudaFuncAttributeMaxDynamicSharedMemorySize, SMEMTOT);

    __nv_bfloat16 *phi_hi, *phi_lo, *W_hi, *W_lo, *q_hi, *q_lo;
    __nv_bfloat16 *kT_hi, *kT_lo, *vT_hi, *vT_lo, *kvT_hi, *kvT_lo;
    float *qkv, *bias;
    cudaGetSymbolAddress((void**)&phi_hi, g_phi_hi);
    cudaGetSymbolAddress((void**)&phi_lo, g_phi_lo);
    cudaGetSymbolAddress((void**)&W_hi,   g_W_hi);
    cudaGetSymbolAddress((void**)&W_lo,   g_W_lo);
    cudaGetSymbolAddress((void**)&q_hi,   g_q_hi);
    cudaGetSymbolAddress((void**)&q_lo,   g_q_lo);
    cudaGetSymbolAddress((void**)&kT_hi,  g_kT_hi);
    cudaGetSymbolAddress((void**)&kT_lo,  g_kT_lo);
    cudaGetSymbolAddress((void**)&vT_hi,  g_vT_hi);
    cudaGetSymbolAddress((void**)&vT_lo,  g_vT_lo);
    cudaGetSymbolAddress((void**)&kvT_hi, g_kvT_hi);
    cudaGetSymbolAddress((void**)&kvT_lo, g_kvT_lo);
    cudaGetSymbolAddress((void**)&qkv,    g_qkv);
    cudaGetSymbolAddress((void**)&bias,   g_bias);

    pack_phi<<<(Mm * Dd) / 1024, 256>>>(phi);
    pack_W<<<QKVC, 128>>>(Wq, bq, Wk, bk, Wv, bv);

    // qkv = phi @ Wcat^T + bias
    mma_gemm<1><<<dim3(QKVC/128, Mm/128, 1), 256, SMEMTOT>>>(
        phi_hi, phi_lo, W_hi, W_lo, Dd, 0, 0,
        qkv, 0, QKVC, bias, nullptr, nullptr, 0);

    rope_split<<<dim3(Mm/32, 4), 256>>>(coords, weights, Wrot);

    // kvT[e,d] = sum_n vT[e,n]*kT[d,n]   (bf16 hi/lo out)
    mma_gemm<2><<<dim3(Dd/128, Dd/128, Bb), 256, SMEMTOT>>>(
        vT_hi, vT_lo, kT_hi, kT_lo, Nn, (size_t)Dd*Nn, (size_t)Dd*Nn,
        nullptr, 0, Dd, nullptr, kvT_hi, kvT_lo, (size_t)Dd*Dd);

    // out[m,e] = sum_d q[m,d]*kvT[e,d]
    mma_gemm<0><<<dim3(Dd/128, Nn/128, Bb), 256, SMEMTOT>>>(
        q_hi, q_lo, kvT_hi, kvT_lo, Dd, (size_t)Nn*Dd, (size_t)Dd*Dd,
        out, (size_t)Nn*Dd, Dd, nullptr, nullptr, nullptr, 0);
}

// round 6
// speedup vs baseline: 1.9933x; 1.0677x over previous
#include <cuda_runtime.h>
#include <cuda_bf16.h>
#include <math.h>
#include <stdint.h>

#define Bb 8
#define Nn 4096
#define Dd 512
#define Mm (Bb*Nn)      // 32768
#define QKVC 1536
#define KVCH 8          // split-K chunks for kv GEMM

// ---------------- scratch (__device__ globals; allocation-free rule) --------
__device__ __nv_bfloat16 g_phi_hi[(size_t)Mm*Dd];
__device__ __nv_bfloat16 g_phi_lo[(size_t)Mm*Dd];
__device__ __nv_bfloat16 g_W_hi[(size_t)QKVC*Dd];
__device__ __nv_bfloat16 g_W_lo[(size_t)QKVC*Dd];
__device__ float         g_bias[QKVC];
__device__ float         g_qkv[(size_t)Mm*QKVC];
__device__ __nv_bfloat16 g_q_hi[(size_t)Mm*Dd];
__device__ __nv_bfloat16 g_q_lo[(size_t)Mm*Dd];
__device__ __nv_bfloat16 g_kT_hi[(size_t)Bb*Dd*Nn];
__device__ __nv_bfloat16 g_kT_lo[(size_t)Bb*Dd*Nn];
__device__ __nv_bfloat16 g_vT_hi[(size_t)Bb*Dd*Nn];
__device__ __nv_bfloat16 g_vT_lo[(size_t)Bb*Dd*Nn];
__device__ float         g_kvp[(size_t)Bb*KVCH*Dd*Dd];   // split-K partials
__device__ __nv_bfloat16 g_kvT_hi[(size_t)Bb*Dd*Dd];
__device__ __nv_bfloat16 g_kvT_lo[(size_t)Bb*Dd*Dd];

// ---------------- helpers ----------------------------------------------------
__device__ __forceinline__ uint32_t smem_u32(const void* p) {
    uint32_t a;
    asm("{ .reg .u64 t; cvta.to.shared.u64 t, %1; cvt.u32.u64 %0, t; }" : "=r"(a) : "l"(p));
    return a;
}
__device__ __forceinline__ void cp16(uint32_t dst, const void* src) {
    asm volatile("cp.async.cg.shared.global [%0], [%1], 16;" :: "r"(dst), "l"(src) : "memory");
}
__device__ __forceinline__ void ldsm4(uint32_t* r, uint32_t addr) {
    asm volatile("ldmatrix.sync.aligned.m8n8.x4.shared.b16 {%0,%1,%2,%3}, [%4];"
                 : "=r"(r[0]), "=r"(r[1]), "=r"(r[2]), "=r"(r[3]) : "r"(addr));
}
__device__ __forceinline__ void mma16816(float* d, const uint32_t* a, const uint32_t* b) {
    asm volatile(
        "mma.sync.aligned.m16n8k16.row.col.f32.bf16.bf16.f32 "
        "{%0,%1,%2,%3}, {%4,%5,%6,%7}, {%8,%9}, {%0,%1,%2,%3};"
        : "+f"(d[0]), "+f"(d[1]), "+f"(d[2]), "+f"(d[3])
        : "r"(a[0]), "r"(a[1]), "r"(a[2]), "r"(a[3]), "r"(b[0]), "r"(b[1]));
}
__device__ __forceinline__ uint32_t packsplit(float v) {
    __nv_bfloat16 h = __float2bfloat16(v);
    __nv_bfloat16 l = __float2bfloat16(v - __bfloat162float(h));
    return (uint32_t)__bfloat16_as_ushort(h) | ((uint32_t)__bfloat16_as_ushort(l) << 16);
}

// ---------------------------------------------------------------------------
// Warp-MMA bf16 split GEMM: D[m,n] = sum_parts A_p[m,:] . B_p[n,:]
// parts: (Ahi,Bhi), (Alo,Bhi), (Ahi,Blo).  Block tile 128x128x32, 8 warps.
// 4-stage cp.async ring, one __syncthreads per k-step.
// blockIdx.z = (batch << bzShift) | chunk ; chunk selects k-range
// [chunk*Kchunk, (chunk+1)*Kchunk). A/B batch offset uses batch; C offset
// uses full bz (per-chunk output slices for split-K).
// EPI: 0 fp32 store, 1 fp32+bias.
// ---------------------------------------------------------------------------
#define RB 80            // row stride bytes (32 bf16 = 64B data + 16B pad)
#define STG (128*RB)     // 10240 B per operand stage
#define SLOT (2*STG)     // A+B per stage
#define SMEMTOT (4*SLOT) // 81920 B

template<int EPI>
__global__ __launch_bounds__(256, 2) void mma_gemm(
    const __nv_bfloat16* __restrict__ Ahi, const __nv_bfloat16* __restrict__ Alo,
    const __nv_bfloat16* __restrict__ Bhi, const __nv_bfloat16* __restrict__ Blo,
    int Kchunk, int ldab, int bzShift, size_t aBS, size_t bBS,
    float* __restrict__ C, size_t cBS, int ldc,
    const float* __restrict__ bias)
{
    extern __shared__ __align__(16) char smem[];
    const uint32_t sbase = smem_u32(smem);
    const int tid  = threadIdx.x;
    const int lane = tid & 31;
    const int wid  = tid >> 5;
    const int wm   = wid >> 2;          // 0..1 (64 rows)
    const int wn   = wid & 3;           // 0..3 (32 cols)
    const int n0 = blockIdx.x * 128;
    const int m0 = blockIdx.y * 128;
    const int bz = blockIdx.z;
    const int b  = bz >> bzShift;
    const int koff = (bz & ((1 << bzShift) - 1)) * Kchunk;

    const int KS = Kchunk >> 5;         // 32-deep k-chunks per part
    const int S  = 3 * KS;
    const __nv_bfloat16* Ap[2] = { Ahi + (size_t)b * aBS, Alo + (size_t)b * aBS };
    const __nv_bfloat16* Bp[2] = { Bhi + (size_t)b * bBS, Blo + (size_t)b * bBS };

    const int lr = tid >> 1;            // loader row 0..127
    const int lc = (tid & 1) * 2;       // 16B chunk 0 or 2

    auto load = [&](int s) {
        int part = s / KS;
        int k0 = koff + ((s - part * KS) << 5);
        const __nv_bfloat16* A = Ap[part == 1];
        const __nv_bfloat16* B = Bp[part == 2];
        uint32_t da = sbase + (s & 3) * SLOT;
        uint32_t db = da + STG;
        const __nv_bfloat16* ag = A + (size_t)(m0 + lr) * ldab + k0 + lc * 8;
        cp16(da + lr * RB + lc * 16, ag);
        cp16(da + lr * RB + lc * 16 + 16, ag + 8);
        const __nv_bfloat16* bg = B + (size_t)(n0 + lr) * ldab + k0 + lc * 8;
        cp16(db + lr * RB + lc * 16, bg);
        cp16(db + lr * RB + lc * 16 + 16, bg + 8);
        asm volatile("cp.async.commit_group;" ::: "memory");
    };

    const uint32_t laA = ((lane & 7) + ((lane >> 3) & 1) * 8) * RB + (lane >> 4) * 16;
    const uint32_t laB = ((lane & 7) + (lane >> 4) * 8) * RB + ((lane >> 3) & 1) * 16;

    float acc[4][4][4] = {};

    load(0); load(1); load(2);

    for (int s = 0; s < S; s++) {
        asm volatile("cp.async.wait_group 2;" ::: "memory");
        __syncthreads();
        if (s + 3 < S) load(s + 3);
        uint32_t sa  = sbase + (s & 3) * SLOT;
        uint32_t sbB = sa + STG;
#pragma unroll
        for (int ks = 0; ks < 2; ks++) {
            uint32_t a[4][4], bfr[2][4];
#pragma unroll
            for (int mf = 0; mf < 4; mf++)
                ldsm4(a[mf], sa + (wm * 64 + mf * 16) * RB + ks * 32 + laA);
#pragma unroll
            for (int bp = 0; bp < 2; bp++)
                ldsm4(bfr[bp], sbB + (wn * 32 + bp * 16) * RB + ks * 32 + laB);
#pragma unroll
            for (int mf = 0; mf < 4; mf++)
#pragma unroll
                for (int nf = 0; nf < 4; nf++)
                    mma16816(acc[mf][nf], a[mf], &bfr[nf >> 1][(nf & 1) * 2]);
        }
    }

    // epilogue
    const int g = lane >> 2;
    const int cq = (lane & 3) * 2;
#pragma unroll
    for (int mf = 0; mf < 4; mf++) {
#pragma unroll
        for (int nf = 0; nf < 4; nf++) {
            int row = m0 + wm * 64 + mf * 16 + g;
            int col = n0 + wn * 32 + nf * 8 + cq;
            float c0 = acc[mf][nf][0], c1 = acc[mf][nf][1];
            float c2 = acc[mf][nf][2], c3 = acc[mf][nf][3];
            float* dst = C + (size_t)bz * cBS + (size_t)row * ldc + col;
            if constexpr (EPI == 0) {
                *(float2*)dst = make_float2(c0, c1);
                *(float2*)(dst + 8 * ldc) = make_float2(c2, c3);
            } else {
                float b0 = __ldg(bias + col), b1 = __ldg(bias + col + 1);
                *(float2*)dst = make_float2(c0 + b0, c1 + b1);
                *(float2*)(dst + 8 * ldc) = make_float2(c2 + b0, c3 + b1);
            }
        }
    }
}

// ---------------------------------------------------------------------------
// Sum the KVCH split-K partial kv slices and emit bf16 hi/lo (deterministic).
// g_kvp layout: [b*KVCH + chunk][512*512] fp32. Each thread handles 2 elems.
// ---------------------------------------------------------------------------
__global__ __launch_bounds__(256) void reduce_pack_kv()
{
    size_t i = ((size_t)blockIdx.x * 256 + threadIdx.x) * 2;
    size_t b   = i >> 18;                 // / (512*512)
    size_t off = i & 262143;
    const float* base = g_kvp + ((size_t)b * KVCH) * 262144 + off;
    float s0 = 0.f, s1 = 0.f;
#pragma unroll
    for (int c = 0; c < KVCH; c++) {
        float2 v = *(const float2*)(base + (size_t)c * 262144);
        s0 += v.x; s1 += v.y;
    }
    uint32_t p0 = packsplit(s0), p1 = packsplit(s1);
    size_t o = (size_t)b * 262144 + off;
    *(uint32_t*)(g_kvT_hi + o) = (p0 & 0xffffu) | (p1 << 16);
    *(uint32_t*)(g_kvT_lo + o) = (p0 >> 16) | (p1 & 0xffff0000u);
}

// ---------------------------------------------------------------------------
__global__ __launch_bounds__(256) void pack_phi(const float* __restrict__ phi)
{
    size_t i = ((size_t)blockIdx.x * 256 + threadIdx.x) * 4;
    float4 x = *(const float4*)(phi + i);
    uint32_t a = packsplit(x.x), b = packsplit(x.y), c = packsplit(x.z), d = packsplit(x.w);
    *(uint32_t*)(g_phi_hi + i)     = (a & 0xffffu) | (b << 16);
    *(uint32_t*)(g_phi_hi + i + 2) = (c & 0xffffu) | (d << 16);
    *(uint32_t*)(g_phi_lo + i)     = (a >> 16) | (b & 0xffff0000u);
    *(uint32_t*)(g_phi_lo + i + 2) = (c >> 16) | (d & 0xffff0000u);
}

__global__ __launch_bounds__(128) void pack_W(
    const float* __restrict__ Wq, const float* __restrict__ bq,
    const float* __restrict__ Wk, const float* __restrict__ bk,
    const float* __restrict__ Wv, const float* __restrict__ bv)
{
    int r = blockIdx.x, t = threadIdx.x;
    const float* src; const float* bs; int sr;
    if (r < 512)       { src = Wq; bs = bq; sr = r; }
    else if (r < 1024) { src = Wk; bs = bk; sr = r - 512; }
    else               { src = Wv; bs = bv; sr = r - 1024; }
    float4 x = *(const float4*)(src + (size_t)sr * Dd + t * 4);
    size_t o = (size_t)r * Dd + t * 4;
    uint32_t a = packsplit(x.x), b = packsplit(x.y), c = packsplit(x.z), d = packsplit(x.w);
    *(uint32_t*)(g_W_hi + o)     = (a & 0xffffu) | (b << 16);
    *(uint32_t*)(g_W_hi + o + 2) = (c & 0xffffu) | (d << 16);
    *(uint32_t*)(g_W_lo + o)     = (a >> 16) | (b & 0xffff0000u);
    *(uint32_t*)(g_W_lo + o + 2) = (c >> 16) | (d & 0xffff0000u);
    if (t == 0) g_bias[r] = bs[sr];
}

// ---------------------------------------------------------------------------
// RoPE + scale + weights + bf16 split; q row-major, k/v transposed to [b,d,n].
// ---------------------------------------------------------------------------
__global__ __launch_bounds__(256) void rope_split(
    const float* __restrict__ coords, const float* __restrict__ weights,
    const float* __restrict__ Wrot)
{
    __shared__ float wr[64][3];
    __shared__ uint32_t sk[128][33];
    __shared__ uint32_t sv[128][33];
    const int t = threadIdx.x;
    const int d0 = blockIdx.y * 64;
    const int row0 = blockIdx.x * 32;
    if (t < 192) wr[t / 3][t % 3] = Wrot[(size_t)(d0 + t / 3) * 3 + (t % 3)];
    __syncthreads();

    const int r  = t >> 3;
    const int c0 = (t & 7) * 8;
    const int row = row0 + r;
    const float x0 = coords[row * 3 + 0], x1 = coords[row * 3 + 1], x2 = coords[row * 3 + 2];
    const float wgt = weights[row];
    const float scale = 0.04419417382415922f;   // 1/sqrt(512)
    const float* src = g_qkv + (size_t)row * QKVC;

    float q0v[8], q1v[8];
#pragma unroll
    for (int j = 0; j < 8; j++) {
        int h = d0 + c0 + j;
        float ph = x0 * wr[c0 + j][0] + x1 * wr[c0 + j][1] + x2 * wr[c0 + j][2];
        float s, c;
        __sincosf(ph, &s, &c);
        float qa = src[h], qb = src[h + 256];
        q0v[j] = (qa * c - qb * s) * scale;
        q1v[j] = (qa * s + qb * c) * scale;
        float ka = src[512 + h], kb = src[512 + h + 256];
        sk[c0 + j][r]      = packsplit(ka * c - kb * s);
        sk[64 + c0 + j][r] = packsplit(ka * s + kb * c);
        sv[c0 + j][r]      = packsplit(src[1024 + h] * wgt);
        sv[64 + c0 + j][r] = packsplit(src[1024 + h + 256] * wgt);
    }
    uint32_t ph0[4], pl0[4], ph1[4], pl1[4];
#pragma unroll
    for (int j = 0; j < 4; j++) {
        uint32_t a = packsplit(q0v[2 * j]), b = packsplit(q0v[2 * j + 1]);
        ph0[j] = (a & 0xffffu) | (b << 16);
        pl0[j] = (a >> 16) | (b & 0xffff0000u);
        uint32_t c = packsplit(q1v[2 * j]), d = packsplit(q1v[2 * j + 1]);
        ph1[j] = (c & 0xffffu) | (d << 16);
        pl1[j] = (c >> 16) | (d & 0xffff0000u);
    }
    size_t qo = (size_t)row * Dd + d0 + c0;
    *(uint4*)(g_q_hi + qo)       = *(uint4*)ph0;
    *(uint4*)(g_q_lo + qo)       = *(uint4*)pl0;
    *(uint4*)(g_q_hi + qo + 256) = *(uint4*)ph1;
    *(uint4*)(g_q_lo + qo + 256) = *(uint4*)pl1;

    __syncthreads();
    const int b   = row0 / Nn;
    const int nn0 = row0 % Nn;
    const int dl  = t >> 1;
    const int j0  = (t & 1) * 16;
    const int dmap = (dl < 64) ? d0 + dl : d0 + 256 + (dl - 64);
    size_t off = ((size_t)b * Dd + dmap) * Nn + nn0 + j0;
    uint32_t hb[8], lb[8];
#pragma unroll
    for (int j = 0; j < 8; j++) {
        uint32_t a = sk[dl][j0 + 2 * j], c = sk[dl][j0 + 2 * j + 1];
        hb[j] = (a & 0xffffu) | (c << 16);
        lb[j] = (a >> 16) | (c & 0xffff0000u);
    }
    *(uint4*)(g_kT_hi + off)     = *(uint4*)hb;
    *(uint4*)(g_kT_hi + off + 8) = *(uint4*)(hb + 4);
    *(uint4*)(g_kT_lo + off)     = *(uint4*)lb;
    *(uint4*)(g_kT_lo + off + 8) = *(uint4*)(lb + 4);
#pragma unroll
    for (int j = 0; j < 8; j++) {
        uint32_t a = sv[dl][j0 + 2 * j], c = sv[dl][j0 + 2 * j + 1];
        hb[j] = (a & 0xffffu) | (c << 16);
        lb[j] = (a >> 16) | (c & 0xffff0000u);
    }
    *(uint4*)(g_vT_hi + off)     = *(uint4*)hb;
    *(uint4*)(g_vT_hi + off + 8) = *(uint4*)(hb + 4);
    *(uint4*)(g_vT_lo + off)     = *(uint4*)lb;
    *(uint4*)(g_vT_lo + off + 8) = *(uint4*)(lb + 4);
}

// ---------------------------------------------------------------------------
extern "C" void kernel_launch(void* const* d_in, const int* in_sizes, int n_in,
                              void* d_out, int out_size)
{
    (void)in_sizes; (void)n_in; (void)out_size;
    const float* phi     = (const float*)d_in[0];
    const float* coords  = (const float*)d_in[1];
    const float* weights = (const float*)d_in[2];
    const float* Wq      = (const float*)d_in[3];
    const float* bq      = (const float*)d_in[4];
    const float* Wk      = (const float*)d_in[5];
    const float* bk      = (const float*)d_in[6];
    const float* Wv      = (const float*)d_in[7];
    const float* bv      = (const float*)d_in[8];
    const float* Wrot    = (const float*)d_in[9];
    float* out = (float*)d_out;

    cudaFuncSetAttribute(mma_gemm<0>, cudaFuncAttributeMaxDynamicSharedMemorySize, SMEMTOT);
    cudaFuncSetAttribute(mma_gemm<1>, cudaFuncAttributeMaxDynamicSharedMemorySize, SMEMTOT);

    __nv_bfloat16 *phi_hi, *phi_lo, *W_hi, *W_lo, *q_hi, *q_lo;
    __nv_bfloat16 *kT_hi, *kT_lo, *vT_hi, *vT_lo, *kvT_hi, *kvT_lo;
    float *qkv, *bias, *kvp;
    cudaGetSymbolAddress((void**)&phi_hi, g_phi_hi);
    cudaGetSymbolAddress((void**)&phi_lo, g_phi_lo);
    cudaGetSymbolAddress((void**)&W_hi,   g_W_hi);
    cudaGetSymbolAddress((void**)&W_lo,   g_W_lo);
    cudaGetSymbolAddress((void**)&q_hi,   g_q_hi);
    cudaGetSymbolAddress((void**)&q_lo,   g_q_lo);
    cudaGetSymbolAddress((void**)&kT_hi,  g_kT_hi);
    cudaGetSymbolAddress((void**)&kT_lo,  g_kT_lo);
    cudaGetSymbolAddress((void**)&vT_hi,  g_vT_hi);
    cudaGetSymbolAddress((void**)&vT_lo,  g_vT_lo);
    cudaGetSymbolAddress((void**)&kvT_hi, g_kvT_hi);
    cudaGetSymbolAddress((void**)&kvT_lo, g_kvT_lo);
    cudaGetSymbolAddress((void**)&qkv,    g_qkv);
    cudaGetSymbolAddress((void**)&bias,   g_bias);
    cudaGetSymbolAddress((void**)&kvp,    g_kvp);

    pack_phi<<<(Mm * Dd) / 1024, 256>>>(phi);
    pack_W<<<QKVC, 128>>>(Wq, bq, Wk, bk, Wv, bv);

    // qkv = phi @ Wcat^T + bias
    mma_gemm<1><<<dim3(QKVC/128, Mm/128, 1), 256, SMEMTOT>>>(
        phi_hi, phi_lo, W_hi, W_lo, Dd, Dd, 0, 0, 0,
        qkv, 0, QKVC, bias);

    rope_split<<<dim3(Mm/32, 4), 256>>>(coords, weights, Wrot);

    // kv split-K: kvp[b,chunk][e,d] = sum_{n in chunk} vT[e,n]*kT[d,n]
    mma_gemm<0><<<dim3(Dd/128, Dd/128, Bb*KVCH), 256, SMEMTOT>>>(
        vT_hi, vT_lo, kT_hi, kT_lo, Nn/KVCH, Nn, 3,
        (size_t)Dd*Nn, (size_t)Dd*Nn,
        kvp, (size_t)Dd*Dd, Dd, nullptr);

    reduce_pack_kv<<<(Bb * Dd * Dd) / 512, 256>>>();

    // out[m,e] = sum_d q[m,d]*kvT[e,d]
    mma_gemm<0><<<dim3(Dd/128, Nn/128, Bb), 256, SMEMTOT>>>(
        q_hi, q_lo, kvT_hi, kvT_lo, Dd, Dd, 0,
        (size_t)Nn*Dd, (size_t)Dd*Dd,
        out, (size_t)Nn*Dd, Dd, nullptr);
}

// round 7
// speedup vs baseline: 2.6967x; 1.3529x over previous
#include <cuda_runtime.h>
#include <cuda_fp16.h>
#include <math.h>
#include <stdint.h>

#define Bb 8
#define Nn 4096
#define Dd 512
#define Mm (Bb*Nn)      // 32768
#define QKVC 1536
#define KVCH 8          // split-K chunks for kv GEMM

// ---------------- scratch (__device__ globals; allocation-free rule) --------
__device__ __half g_phi_hi[(size_t)Mm*Dd];
__device__ __half g_phi_lo[(size_t)Mm*Dd];
__device__ __half g_W_hi[(size_t)QKVC*Dd];
__device__ float  g_bias[QKVC];
__device__ float  g_qkv[(size_t)Mm*QKVC];
__device__ __half g_q_hi[(size_t)Mm*Dd];
__device__ __half g_q_lo[(size_t)Mm*Dd];
__device__ __half g_kT_hi[(size_t)Bb*Dd*Nn];
__device__ __half g_vT_hi[(size_t)Bb*Dd*Nn];
__device__ __half g_vT_lo[(size_t)Bb*Dd*Nn];
__device__ float  g_kvp[(size_t)Bb*KVCH*Dd*Dd];   // split-K partials
__device__ __half g_kvT_hi[(size_t)Bb*Dd*Dd];

// ---------------- helpers ----------------------------------------------------
__device__ __forceinline__ uint32_t smem_u32(const void* p) {
    uint32_t a;
    asm("{ .reg .u64 t; cvta.to.shared.u64 t, %1; cvt.u32.u64 %0, t; }" : "=r"(a) : "l"(p));
    return a;
}
__device__ __forceinline__ void cp16(uint32_t dst, const void* src) {
    asm volatile("cp.async.cg.shared.global [%0], [%1], 16;" :: "r"(dst), "l"(src) : "memory");
}
__device__ __forceinline__ void ldsm4(uint32_t* r, uint32_t addr) {
    asm volatile("ldmatrix.sync.aligned.m8n8.x4.shared.b16 {%0,%1,%2,%3}, [%4];"
                 : "=r"(r[0]), "=r"(r[1]), "=r"(r[2]), "=r"(r[3]) : "r"(addr));
}
__device__ __forceinline__ void mma16816(float* d, const uint32_t* a, const uint32_t* b) {
    asm volatile(
        "mma.sync.aligned.m16n8k16.row.col.f32.f16.f16.f32 "
        "{%0,%1,%2,%3}, {%4,%5,%6,%7}, {%8,%9}, {%0,%1,%2,%3};"
        : "+f"(d[0]), "+f"(d[1]), "+f"(d[2]), "+f"(d[3])
        : "r"(a[0]), "r"(a[1]), "r"(a[2]), "r"(a[3]), "r"(b[0]), "r"(b[1]));
}
__device__ __forceinline__ uint32_t packsplit(float v) {
    __half h = __float2half_rn(v);
    __half l = __float2half_rn(v - __half2float(h));
    return (uint32_t)__half_as_ushort(h) | ((uint32_t)__half_as_ushort(l) << 16);
}

// ---------------------------------------------------------------------------
// Warp-MMA fp16 2-term split GEMM: D[m,n] = (Ahi+Alo)[m,:] . Bhi[n,:]
// Block tile 128x128x32, 8 warps, 4-stage cp.async ring.
// blockIdx.z = (batch << bzShift) | chunk ; chunk selects k-range.
// EPI: 0 fp32 store, 1 fp32+bias.
// ---------------------------------------------------------------------------
#define RB 80            // row stride bytes (32 fp16 = 64B data + 16B pad)
#define STG (128*RB)     // 10240 B per operand stage
#define SLOT (2*STG)     // A+B per stage
#define SMEMTOT (4*SLOT) // 81920 B

template<int EPI>
__global__ __launch_bounds__(256, 2) void mma_gemm(
    const __half* __restrict__ Ahi, const __half* __restrict__ Alo,
    const __half* __restrict__ Bhi,
    int Kchunk, int ldab, int bzShift, size_t aBS, size_t bBS,
    float* __restrict__ C, size_t cBS, int ldc,
    const float* __restrict__ bias)
{
    extern __shared__ __align__(16) char smem[];
    const uint32_t sbase = smem_u32(smem);
    const int tid  = threadIdx.x;
    const int lane = tid & 31;
    const int wid  = tid >> 5;
    const int wm   = wid >> 2;          // 0..1 (64 rows)
    const int wn   = wid & 3;           // 0..3 (32 cols)
    const int n0 = blockIdx.x * 128;
    const int m0 = blockIdx.y * 128;
    const int bz = blockIdx.z;
    const int b  = bz >> bzShift;
    const int koff = (bz & ((1 << bzShift) - 1)) * Kchunk;

    const int KS = Kchunk >> 5;         // 32-deep k-chunks per part
    const int S  = 2 * KS;
    const __half* Ap[2] = { Ahi + (size_t)b * aBS, Alo + (size_t)b * aBS };
    const __half* Bp    = Bhi + (size_t)b * bBS;

    const int lr = tid >> 1;            // loader row 0..127
    const int lc = (tid & 1) * 2;       // 16B chunk 0 or 2

    auto load = [&](int s) {
        int part = s >= KS;
        int k0 = koff + ((s - (part ? KS : 0)) << 5);
        const __half* A = Ap[part];
        uint32_t da = sbase + (s & 3) * SLOT;
        uint32_t db = da + STG;
        const __half* ag = A + (size_t)(m0 + lr) * ldab + k0 + lc * 8;
        cp16(da + lr * RB + lc * 16, ag);
        cp16(da + lr * RB + lc * 16 + 16, ag + 8);
        const __half* bg = Bp + (size_t)(n0 + lr) * ldab + k0 + lc * 8;
        cp16(db + lr * RB + lc * 16, bg);
        cp16(db + lr * RB + lc * 16 + 16, bg + 8);
        asm volatile("cp.async.commit_group;" ::: "memory");
    };

    const uint32_t laA = ((lane & 7) + ((lane >> 3) & 1) * 8) * RB + (lane >> 4) * 16;
    const uint32_t laB = ((lane & 7) + (lane >> 4) * 8) * RB + ((lane >> 3) & 1) * 16;

    float acc[4][4][4] = {};

    load(0); load(1); load(2);

    for (int s = 0; s < S; s++) {
        asm volatile("cp.async.wait_group 2;" ::: "memory");
        __syncthreads();
        if (s + 3 < S) load(s + 3);
        uint32_t sa  = sbase + (s & 3) * SLOT;
        uint32_t sbB = sa + STG;
#pragma unroll
        for (int ks = 0; ks < 2; ks++) {
            uint32_t a[4][4], bfr[2][4];
#pragma unroll
            for (int mf = 0; mf < 4; mf++)
                ldsm4(a[mf], sa + (wm * 64 + mf * 16) * RB + ks * 32 + laA);
#pragma unroll
            for (int bp = 0; bp < 2; bp++)
                ldsm4(bfr[bp], sbB + (wn * 32 + bp * 16) * RB + ks * 32 + laB);
#pragma unroll
            for (int mf = 0; mf < 4; mf++)
#pragma unroll
                for (int nf = 0; nf < 4; nf++)
                    mma16816(acc[mf][nf], a[mf], &bfr[nf >> 1][(nf & 1) * 2]);
        }
    }

    // epilogue
    const int g = lane >> 2;
    const int cq = (lane & 3) * 2;
#pragma unroll
    for (int mf = 0; mf < 4; mf++) {
#pragma unroll
        for (int nf = 0; nf < 4; nf++) {
            int row = m0 + wm * 64 + mf * 16 + g;
            int col = n0 + wn * 32 + nf * 8 + cq;
            float c0 = acc[mf][nf][0], c1 = acc[mf][nf][1];
            float c2 = acc[mf][nf][2], c3 = acc[mf][nf][3];
            float* dst = C + (size_t)bz * cBS + (size_t)row * ldc + col;
            if constexpr (EPI == 0) {
                *(float2*)dst = make_float2(c0, c1);
                *(float2*)(dst + 8 * ldc) = make_float2(c2, c3);
            } else {
                float b0 = __ldg(bias + col), b1 = __ldg(bias + col + 1);
                *(float2*)dst = make_float2(c0 + b0, c1 + b1);
                *(float2*)(dst + 8 * ldc) = make_float2(c2 + b0, c3 + b1);
            }
        }
    }
}

// ---------------------------------------------------------------------------
// Sum KVCH split-K partial kv slices, emit fp16 hi (B operand of GEMM3).
// ---------------------------------------------------------------------------
__global__ __launch_bounds__(256) void reduce_pack_kv()
{
    size_t i = ((size_t)blockIdx.x * 256 + threadIdx.x) * 2;
    size_t b   = i >> 18;                 // / (512*512)
    size_t off = i & 262143;
    const float* base = g_kvp + ((size_t)b * KVCH) * 262144 + off;
    float s0 = 0.f, s1 = 0.f;
#pragma unroll
    for (int c = 0; c < KVCH; c++) {
        float2 v = *(const float2*)(base + (size_t)c * 262144);
        s0 += v.x; s1 += v.y;
    }
    __half h0 = __float2half_rn(s0), h1 = __float2half_rn(s1);
    size_t o = (size_t)b * 262144 + off;
    *(uint32_t*)(g_kvT_hi + o) =
        (uint32_t)__half_as_ushort(h0) | ((uint32_t)__half_as_ushort(h1) << 16);
}

// ---------------------------------------------------------------------------
__global__ __launch_bounds__(256) void pack_phi(const float* __restrict__ phi)
{
    size_t i = ((size_t)blockIdx.x * 256 + threadIdx.x) * 4;
    float4 x = *(const float4*)(phi + i);
    uint32_t a = packsplit(x.x), b = packsplit(x.y), c = packsplit(x.z), d = packsplit(x.w);
    *(uint32_t*)(g_phi_hi + i)     = (a & 0xffffu) | (b << 16);
    *(uint32_t*)(g_phi_hi + i + 2) = (c & 0xffffu) | (d << 16);
    *(uint32_t*)(g_phi_lo + i)     = (a >> 16) | (b & 0xffff0000u);
    *(uint32_t*)(g_phi_lo + i + 2) = (c >> 16) | (d & 0xffff0000u);
}

__global__ __launch_bounds__(128) void pack_W(
    const float* __restrict__ Wq, const float* __restrict__ bq,
    const float* __restrict__ Wk, const float* __restrict__ bk,
    const float* __restrict__ Wv, const float* __restrict__ bv)
{
    int r = blockIdx.x, t = threadIdx.x;
    const float* src; const float* bs; int sr;
    if (r < 512)       { src = Wq; bs = bq; sr = r; }
    else if (r < 1024) { src = Wk; bs = bk; sr = r - 512; }
    else               { src = Wv; bs = bv; sr = r - 1024; }
    float4 x = *(const float4*)(src + (size_t)sr * Dd + t * 4);
    size_t o = (size_t)r * Dd + t * 4;
    __half h0 = __float2half_rn(x.x), h1 = __float2half_rn(x.y);
    __half h2 = __float2half_rn(x.z), h3 = __float2half_rn(x.w);
    *(uint32_t*)(g_W_hi + o) =
        (uint32_t)__half_as_ushort(h0) | ((uint32_t)__half_as_ushort(h1) << 16);
    *(uint32_t*)(g_W_hi + o + 2) =
        (uint32_t)__half_as_ushort(h2) | ((uint32_t)__half_as_ushort(h3) << 16);
    if (t == 0) g_bias[r] = bs[sr];
}

// ---------------------------------------------------------------------------
// RoPE + scale + weights + fp16 split; q row-major (hi/lo),
// kT hi-only / vT hi+lo transposed to [b,d,n].
// ---------------------------------------------------------------------------
__global__ __launch_bounds__(256) void rope_split(
    const float* __restrict__ coords, const float* __restrict__ weights,
    const float* __restrict__ Wrot)
{
    __shared__ float wr[64][3];
    __shared__ uint32_t sk[128][33];
    __shared__ uint32_t sv[128][33];
    const int t = threadIdx.x;
    const int d0 = blockIdx.y * 64;
    const int row0 = blockIdx.x * 32;
    if (t < 192) wr[t / 3][t % 3] = Wrot[(size_t)(d0 + t / 3) * 3 + (t % 3)];
    __syncthreads();

    const int r  = t >> 3;
    const int c0 = (t & 7) * 8;
    const int row = row0 + r;
    const float x0 = coords[row * 3 + 0], x1 = coords[row * 3 + 1], x2 = coords[row * 3 + 2];
    const float wgt = weights[row];
    const float scale = 0.04419417382415922f;   // 1/sqrt(512)
    const float* src = g_qkv + (size_t)row * QKVC;

    float q0v[8], q1v[8];
#pragma unroll
    for (int j = 0; j < 8; j++) {
        int h = d0 + c0 + j;
        float ph = x0 * wr[c0 + j][0] + x1 * wr[c0 + j][1] + x2 * wr[c0 + j][2];
        float s, c;
        __sincosf(ph, &s, &c);
        float qa = src[h], qb = src[h + 256];
        q0v[j] = (qa * c - qb * s) * scale;
        q1v[j] = (qa * s + qb * c) * scale;
        float ka = src[512 + h], kb = src[512 + h + 256];
        sk[c0 + j][r]      = packsplit(ka * c - kb * s);
        sk[64 + c0 + j][r] = packsplit(ka * s + kb * c);
        sv[c0 + j][r]      = packsplit(src[1024 + h] * wgt);
        sv[64 + c0 + j][r] = packsplit(src[1024 + h + 256] * wgt);
    }
    uint32_t ph0[4], pl0[4], ph1[4], pl1[4];
#pragma unroll
    for (int j = 0; j < 4; j++) {
        uint32_t a = packsplit(q0v[2 * j]), b = packsplit(q0v[2 * j + 1]);
        ph0[j] = (a & 0xffffu) | (b << 16);
        pl0[j] = (a >> 16) | (b & 0xffff0000u);
        uint32_t c = packsplit(q1v[2 * j]), d = packsplit(q1v[2 * j + 1]);
        ph1[j] = (c & 0xffffu) | (d << 16);
        pl1[j] = (c >> 16) | (d & 0xffff0000u);
    }
    size_t qo = (size_t)row * Dd + d0 + c0;
    *(uint4*)(g_q_hi + qo)       = *(uint4*)ph0;
    *(uint4*)(g_q_lo + qo)       = *(uint4*)pl0;
    *(uint4*)(g_q_hi + qo + 256) = *(uint4*)ph1;
    *(uint4*)(g_q_lo + qo + 256) = *(uint4*)pl1;

    __syncthreads();
    const int b   = row0 / Nn;
    const int nn0 = row0 % Nn;
    const int dl  = t >> 1;
    const int j0  = (t & 1) * 16;
    const int dmap = (dl < 64) ? d0 + dl : d0 + 256 + (dl - 64);
    size_t off = ((size_t)b * Dd + dmap) * Nn + nn0 + j0;
    uint32_t hb[8], lb[8];
#pragma unroll
    for (int j = 0; j < 8; j++) {
        uint32_t a = sk[dl][j0 + 2 * j], c = sk[dl][j0 + 2 * j + 1];
        hb[j] = (a & 0xffffu) | (c << 16);
    }
    *(uint4*)(g_kT_hi + off)     = *(uint4*)hb;
    *(uint4*)(g_kT_hi + off + 8) = *(uint4*)(hb + 4);
#pragma unroll
    for (int j = 0; j < 8; j++) {
        uint32_t a = sv[dl][j0 + 2 * j], c = sv[dl][j0 + 2 * j + 1];
        hb[j] = (a & 0xffffu) | (c << 16);
        lb[j] = (a >> 16) | (c & 0xffff0000u);
    }
    *(uint4*)(g_vT_hi + off)     = *(uint4*)hb;
    *(uint4*)(g_vT_hi + off + 8) = *(uint4*)(hb + 4);
    *(uint4*)(g_vT_lo + off)     = *(uint4*)lb;
    *(uint4*)(g_vT_lo + off + 8) = *(uint4*)(lb + 4);
}

// ---------------------------------------------------------------------------
extern "C" void kernel_launch(void* const* d_in, const int* in_sizes, int n_in,
                              void* d_out, int out_size)
{
    (void)in_sizes; (void)n_in; (void)out_size;
    const float* phi     = (const float*)d_in[0];
    const float* coords  = (const float*)d_in[1];
    const float* weights = (const float*)d_in[2];
    const float* Wq      = (const float*)d_in[3];
    const float* bq      = (const float*)d_in[4];
    const float* Wk      = (const float*)d_in[5];
    const float* bk      = (const float*)d_in[6];
    const float* Wv      = (const float*)d_in[7];
    const float* bv      = (const float*)d_in[8];
    const float* Wrot    = (const float*)d_in[9];
    float* out = (float*)d_out;

    cudaFuncSetAttribute(mma_gemm<0>, cudaFuncAttributeMaxDynamicSharedMemorySize, SMEMTOT);
    cudaFuncSetAttribute(mma_gemm<1>, cudaFuncAttributeMaxDynamicSharedMemorySize, SMEMTOT);

    __half *phi_hi, *phi_lo, *W_hi, *q_hi, *q_lo;
    __half *kT_hi, *vT_hi, *vT_lo, *kvT_hi;
    float *qkv, *bias, *kvp;
    cudaGetSymbolAddress((void**)&phi_hi, g_phi_hi);
    cudaGetSymbolAddress((void**)&phi_lo, g_phi_lo);
    cudaGetSymbolAddress((void**)&W_hi,   g_W_hi);
    cudaGetSymbolAddress((void**)&q_hi,   g_q_hi);
    cudaGetSymbolAddress((void**)&q_lo,   g_q_lo);
    cudaGetSymbolAddress((void**)&kT_hi,  g_kT_hi);
    cudaGetSymbolAddress((void**)&vT_hi,  g_vT_hi);
    cudaGetSymbolAddress((void**)&vT_lo,  g_vT_lo);
    cudaGetSymbolAddress((void**)&kvT_hi, g_kvT_hi);
    cudaGetSymbolAddress((void**)&qkv,    g_qkv);
    cudaGetSymbolAddress((void**)&bias,   g_bias);
    cudaGetSymbolAddress((void**)&kvp,    g_kvp);

    pack_phi<<<(Mm * Dd) / 1024, 256>>>(phi);
    pack_W<<<QKVC, 128>>>(Wq, bq, Wk, bk, Wv, bv);

    // qkv = phi @ Wcat^T + bias
    mma_gemm<1><<<dim3(QKVC/128, Mm/128, 1), 256, SMEMTOT>>>(
        phi_hi, phi_lo, W_hi, Dd, Dd, 0, 0, 0,
        qkv, 0, QKVC, bias);

    rope_split<<<dim3(Mm/32, 4), 256>>>(coords, weights, Wrot);

    // kv split-K: kvp[b,chunk][e,d] = sum_{n in chunk} vT[e,n]*kT[d,n]
    mma_gemm<0><<<dim3(Dd/128, Dd/128, Bb*KVCH), 256, SMEMTOT>>>(
        vT_hi, vT_lo, kT_hi, Nn/KVCH, Nn, 3,
        (size_t)Dd*Nn, (size_t)Dd*Nn,
        kvp, (size_t)Dd*Dd, Dd, nullptr);

    reduce_pack_kv<<<(Bb * Dd * Dd) / 512, 256>>>();

    // out[m,e] = sum_d q[m,d]*kvT[e,d]
    mma_gemm<0><<<dim3(Dd/128, Nn/128, Bb), 256, SMEMTOT>>>(
        q_hi, q_lo, kvT_hi, Dd, Dd, 0,
        (size_t)Nn*Dd, (size_t)Dd*Dd,
        out, (size_t)Nn*Dd, Dd, nullptr);
}

// round 8
// speedup vs baseline: 3.3547x; 1.2440x over previous
#include <cuda_runtime.h>
#include <cuda_fp16.h>
#include <math.h>
#include <stdint.h>

#define Bb 8
#define Nn 4096
#define Dd 512
#define Mm (Bb*Nn)      // 32768
#define QKVC 1536
#define KVCH 8          // split-K chunks for kv GEMM

// ---------------- scratch (__device__ globals; allocation-free rule) --------
__device__ __half g_phi_hi[(size_t)Mm*Dd];
__device__ __half g_phi_lo[(size_t)Mm*Dd];
__device__ __half g_W_hi[(size_t)QKVC*Dd];
__device__ float  g_bias[QKVC];
__device__ float  g_qkv[(size_t)Mm*QKVC];
__device__ __half g_q_hi[(size_t)Mm*Dd];
__device__ __half g_kT_hi[(size_t)Bb*Dd*Nn];
__device__ __half g_vT_hi[(size_t)Bb*Dd*Nn];
__device__ float  g_kvp[(size_t)Bb*KVCH*Dd*Dd];   // split-K partials
__device__ __half g_kvT_hi[(size_t)Bb*Dd*Dd];

// ---------------- helpers ----------------------------------------------------
__device__ __forceinline__ uint32_t smem_u32(const void* p) {
    uint32_t a;
    asm("{ .reg .u64 t; cvta.to.shared.u64 t, %1; cvt.u32.u64 %0, t; }" : "=r"(a) : "l"(p));
    return a;
}
__device__ __forceinline__ void cp16(uint32_t dst, const void* src) {
    asm volatile("cp.async.cg.shared.global [%0], [%1], 16;" :: "r"(dst), "l"(src) : "memory");
}
__device__ __forceinline__ void ldsm4(uint32_t* r, uint32_t addr) {
    asm volatile("ldmatrix.sync.aligned.m8n8.x4.shared.b16 {%0,%1,%2,%3}, [%4];"
                 : "=r"(r[0]), "=r"(r[1]), "=r"(r[2]), "=r"(r[3]) : "r"(addr));
}
__device__ __forceinline__ void mma16816(float* d, const uint32_t* a, const uint32_t* b) {
    asm volatile(
        "mma.sync.aligned.m16n8k16.row.col.f32.f16.f16.f32 "
        "{%0,%1,%2,%3}, {%4,%5,%6,%7}, {%8,%9}, {%0,%1,%2,%3};"
        : "+f"(d[0]), "+f"(d[1]), "+f"(d[2]), "+f"(d[3])
        : "r"(a[0]), "r"(a[1]), "r"(a[2]), "r"(a[3]), "r"(b[0]), "r"(b[1]));
}
__device__ __forceinline__ uint32_t packsplit(float v) {
    __half h = __float2half_rn(v);
    __half l = __float2half_rn(v - __half2float(h));
    return (uint32_t)__half_as_ushort(h) | ((uint32_t)__half_as_ushort(l) << 16);
}

// ---------------------------------------------------------------------------
// Warp-MMA fp16 split GEMM: D[m,n] = (Ahi [+ Alo])[m,:] . Bhi[n,:]
// PARTS = 1 (A hi only) or 2 (hi+lo). Block tile 128x128x32, 8 warps,
// 4-stage cp.async ring. blockIdx.z = (batch << bzShift) | chunk.
// EPI: 0 fp32 store, 1 fp32+bias.
// ---------------------------------------------------------------------------
#define RB 80            // row stride bytes (32 fp16 = 64B data + 16B pad)
#define STG (128*RB)     // 10240 B per operand stage
#define SLOT (2*STG)     // A+B per stage
#define SMEMTOT (4*SLOT) // 81920 B

template<int EPI, int PARTS>
__global__ __launch_bounds__(256, 2) void mma_gemm(
    const __half* __restrict__ Ahi, const __half* __restrict__ Alo,
    const __half* __restrict__ Bhi,
    int Kchunk, int ldab, int bzShift, size_t aBS, size_t bBS,
    float* __restrict__ C, size_t cBS, int ldc,
    const float* __restrict__ bias)
{
    extern __shared__ __align__(16) char smem[];
    const uint32_t sbase = smem_u32(smem);
    const int tid  = threadIdx.x;
    const int lane = tid & 31;
    const int wid  = tid >> 5;
    const int wm   = wid >> 2;          // 0..1 (64 rows)
    const int wn   = wid & 3;           // 0..3 (32 cols)
    const int n0 = blockIdx.x * 128;
    const int m0 = blockIdx.y * 128;
    const int bz = blockIdx.z;
    const int b  = bz >> bzShift;
    const int koff = (bz & ((1 << bzShift) - 1)) * Kchunk;

    const int KS = Kchunk >> 5;         // 32-deep k-chunks per part
    const int S  = PARTS * KS;
    const __half* Ap[2] = { Ahi + (size_t)b * aBS,
                            (PARTS == 2 ? Alo + (size_t)b * aBS : Ahi) };
    const __half* Bp    = Bhi + (size_t)b * bBS;

    const int lr = tid >> 1;            // loader row 0..127
    const int lc = (tid & 1) * 2;       // 16B chunk 0 or 2

    auto load = [&](int s) {
        int part = (PARTS == 2) ? (s >= KS) : 0;
        int k0 = koff + ((s - (part ? KS : 0)) << 5);
        const __half* A = Ap[part];
        uint32_t da = sbase + (s & 3) * SLOT;
        uint32_t db = da + STG;
        const __half* ag = A + (size_t)(m0 + lr) * ldab + k0 + lc * 8;
        cp16(da + lr * RB + lc * 16, ag);
        cp16(da + lr * RB + lc * 16 + 16, ag + 8);
        const __half* bg = Bp + (size_t)(n0 + lr) * ldab + k0 + lc * 8;
        cp16(db + lr * RB + lc * 16, bg);
        cp16(db + lr * RB + lc * 16 + 16, bg + 8);
        asm volatile("cp.async.commit_group;" ::: "memory");
    };

    const uint32_t laA = ((lane & 7) + ((lane >> 3) & 1) * 8) * RB + (lane >> 4) * 16;
    const uint32_t laB = ((lane & 7) + (lane >> 4) * 8) * RB + ((lane >> 3) & 1) * 16;

    float acc[4][4][4] = {};

    load(0); load(1); load(2);

    for (int s = 0; s < S; s++) {
        asm volatile("cp.async.wait_group 2;" ::: "memory");
        __syncthreads();
        if (s + 3 < S) load(s + 3);
        uint32_t sa  = sbase + (s & 3) * SLOT;
        uint32_t sbB = sa + STG;
#pragma unroll
        for (int ks = 0; ks < 2; ks++) {
            uint32_t a[4][4], bfr[2][4];
#pragma unroll
            for (int mf = 0; mf < 4; mf++)
                ldsm4(a[mf], sa + (wm * 64 + mf * 16) * RB + ks * 32 + laA);
#pragma unroll
            for (int bp = 0; bp < 2; bp++)
                ldsm4(bfr[bp], sbB + (wn * 32 + bp * 16) * RB + ks * 32 + laB);
#pragma unroll
            for (int mf = 0; mf < 4; mf++)
#pragma unroll
                for (int nf = 0; nf < 4; nf++)
                    mma16816(acc[mf][nf], a[mf], &bfr[nf >> 1][(nf & 1) * 2]);
        }
    }

    // epilogue
    const int g = lane >> 2;
    const int cq = (lane & 3) * 2;
#pragma unroll
    for (int mf = 0; mf < 4; mf++) {
#pragma unroll
        for (int nf = 0; nf < 4; nf++) {
            int row = m0 + wm * 64 + mf * 16 + g;
            int col = n0 + wn * 32 + nf * 8 + cq;
            float c0 = acc[mf][nf][0], c1 = acc[mf][nf][1];
            float c2 = acc[mf][nf][2], c3 = acc[mf][nf][3];
            float* dst = C + (size_t)bz * cBS + (size_t)row * ldc + col;
            if constexpr (EPI == 0) {
                *(float2*)dst = make_float2(c0, c1);
                *(float2*)(dst + 8 * ldc) = make_float2(c2, c3);
            } else {
                float b0 = __ldg(bias + col), b1 = __ldg(bias + col + 1);
                *(float2*)dst = make_float2(c0 + b0, c1 + b1);
                *(float2*)(dst + 8 * ldc) = make_float2(c2 + b0, c3 + b1);
            }
        }
    }
}

// ---------------------------------------------------------------------------
// Sum KVCH split-K partial kv slices, emit fp16 hi (B operand of GEMM3).
// ---------------------------------------------------------------------------
__global__ __launch_bounds__(256) void reduce_pack_kv()
{
    size_t i = ((size_t)blockIdx.x * 256 + threadIdx.x) * 2;
    size_t b   = i >> 18;                 // / (512*512)
    size_t off = i & 262143;
    const float* base = g_kvp + ((size_t)b * KVCH) * 262144 + off;
    float s0 = 0.f, s1 = 0.f;
#pragma unroll
    for (int c = 0; c < KVCH; c++) {
        float2 v = *(const float2*)(base + (size_t)c * 262144);
        s0 += v.x; s1 += v.y;
    }
    __half h0 = __float2half_rn(s0), h1 = __float2half_rn(s1);
    size_t o = (size_t)b * 262144 + off;
    *(uint32_t*)(g_kvT_hi + o) =
        (uint32_t)__half_as_ushort(h0) | ((uint32_t)__half_as_ushort(h1) << 16);
}

// ---------------------------------------------------------------------------
__global__ __launch_bounds__(256) void pack_phi(const float* __restrict__ phi)
{
    size_t i = ((size_t)blockIdx.x * 256 + threadIdx.x) * 4;
    float4 x = *(const float4*)(phi + i);
    uint32_t a = packsplit(x.x), b = packsplit(x.y), c = packsplit(x.z), d = packsplit(x.w);
    *(uint32_t*)(g_phi_hi + i)     = (a & 0xffffu) | (b << 16);
    *(uint32_t*)(g_phi_hi + i + 2) = (c & 0xffffu) | (d << 16);
    *(uint32_t*)(g_phi_lo + i)     = (a >> 16) | (b & 0xffff0000u);
    *(uint32_t*)(g_phi_lo + i + 2) = (c >> 16) | (d & 0xffff0000u);
}

__global__ __launch_bounds__(128) void pack_W(
    const float* __restrict__ Wq, const float* __restrict__ bq,
    const float* __restrict__ Wk, const float* __restrict__ bk,
    const float* __restrict__ Wv, const float* __restrict__ bv)
{
    int r = blockIdx.x, t = threadIdx.x;
    const float* src; const float* bs; int sr;
    if (r < 512)       { src = Wq; bs = bq; sr = r; }
    else if (r < 1024) { src = Wk; bs = bk; sr = r - 512; }
    else               { src = Wv; bs = bv; sr = r - 1024; }
    float4 x = *(const float4*)(src + (size_t)sr * Dd + t * 4);
    size_t o = (size_t)r * Dd + t * 4;
    __half h0 = __float2half_rn(x.x), h1 = __float2half_rn(x.y);
    __half h2 = __float2half_rn(x.z), h3 = __float2half_rn(x.w);
    *(uint32_t*)(g_W_hi + o) =
        (uint32_t)__half_as_ushort(h0) | ((uint32_t)__half_as_ushort(h1) << 16);
    *(uint32_t*)(g_W_hi + o + 2) =
        (uint32_t)__half_as_ushort(h2) | ((uint32_t)__half_as_ushort(h3) << 16);
    if (t == 0) g_bias[r] = bs[sr];
}

// ---------------------------------------------------------------------------
// RoPE + scale + weights + fp16; q hi row-major, kT/vT hi transposed [b,d,n].
// ---------------------------------------------------------------------------
__global__ __launch_bounds__(256) void rope_split(
    const float* __restrict__ coords, const float* __restrict__ weights,
    const float* __restrict__ Wrot)
{
    __shared__ float wr[64][3];
    __shared__ uint16_t sk[128][36];
    __shared__ uint16_t sv[128][36];
    const int t = threadIdx.x;
    const int d0 = blockIdx.y * 64;
    const int row0 = blockIdx.x * 32;
    if (t < 192) wr[t / 3][t % 3] = Wrot[(size_t)(d0 + t / 3) * 3 + (t % 3)];
    __syncthreads();

    const int r  = t >> 3;
    const int c0 = (t & 7) * 8;
    const int row = row0 + r;
    const float x0 = coords[row * 3 + 0], x1 = coords[row * 3 + 1], x2 = coords[row * 3 + 2];
    const float wgt = weights[row];
    const float scale = 0.04419417382415922f;   // 1/sqrt(512)
    const float* src = g_qkv + (size_t)row * QKVC;

    float q0v[8], q1v[8];
#pragma unroll
    for (int j = 0; j < 8; j++) {
        int h = d0 + c0 + j;
        float ph = x0 * wr[c0 + j][0] + x1 * wr[c0 + j][1] + x2 * wr[c0 + j][2];
        float s, c;
        __sincosf(ph, &s, &c);
        float qa = src[h], qb = src[h + 256];
        q0v[j] = (qa * c - qb * s) * scale;
        q1v[j] = (qa * s + qb * c) * scale;
        float ka = src[512 + h], kb = src[512 + h + 256];
        sk[c0 + j][r]      = __half_as_ushort(__float2half_rn(ka * c - kb * s));
        sk[64 + c0 + j][r] = __half_as_ushort(__float2half_rn(ka * s + kb * c));
        sv[c0 + j][r]      = __half_as_ushort(__float2half_rn(src[1024 + h] * wgt));
        sv[64 + c0 + j][r] = __half_as_ushort(__float2half_rn(src[1024 + h + 256] * wgt));
    }
    uint32_t ph0[4], ph1[4];
#pragma unroll
    for (int j = 0; j < 4; j++) {
        __half a = __float2half_rn(q0v[2 * j]), b = __float2half_rn(q0v[2 * j + 1]);
        ph0[j] = (uint32_t)__half_as_ushort(a) | ((uint32_t)__half_as_ushort(b) << 16);
        __half c = __float2half_rn(q1v[2 * j]), d = __float2half_rn(q1v[2 * j + 1]);
        ph1[j] = (uint32_t)__half_as_ushort(c) | ((uint32_t)__half_as_ushort(d) << 16);
    }
    size_t qo = (size_t)row * Dd + d0 + c0;
    *(uint4*)(g_q_hi + qo)       = *(uint4*)ph0;
    *(uint4*)(g_q_hi + qo + 256) = *(uint4*)ph1;

    __syncthreads();
    const int b   = row0 / Nn;
    const int nn0 = row0 % Nn;
    const int dl  = t >> 1;
    const int j0  = (t & 1) * 16;
    const int dmap = (dl < 64) ? d0 + dl : d0 + 256 + (dl - 64);
    size_t off = ((size_t)b * Dd + dmap) * Nn + nn0 + j0;
    uint32_t hb[8];
#pragma unroll
    for (int j = 0; j < 8; j++)
        hb[j] = (uint32_t)sk[dl][j0 + 2 * j] | ((uint32_t)sk[dl][j0 + 2 * j + 1] << 16);
    *(uint4*)(g_kT_hi + off)     = *(uint4*)hb;
    *(uint4*)(g_kT_hi + off + 8) = *(uint4*)(hb + 4);
#pragma unroll
    for (int j = 0; j < 8; j++)
        hb[j] = (uint32_t)sv[dl][j0 + 2 * j] | ((uint32_t)sv[dl][j0 + 2 * j + 1] << 16);
    *(uint4*)(g_vT_hi + off)     = *(uint4*)hb;
    *(uint4*)(g_vT_hi + off + 8) = *(uint4*)(hb + 4);
}

// ---------------------------------------------------------------------------
extern "C" void kernel_launch(void* const* d_in, const int* in_sizes, int n_in,
                              void* d_out, int out_size)
{
    (void)in_sizes; (void)n_in; (void)out_size;
    const float* phi     = (const float*)d_in[0];
    const float* coords  = (const float*)d_in[1];
    const float* weights = (const float*)d_in[2];
    const float* Wq      = (const float*)d_in[3];
    const float* bq      = (const float*)d_in[4];
    const float* Wk      = (const float*)d_in[5];
    const float* bk      = (const float*)d_in[6];
    const float* Wv      = (const float*)d_in[7];
    const float* bv      = (const float*)d_in[8];
    const float* Wrot    = (const float*)d_in[9];
    float* out = (float*)d_out;

    cudaFuncSetAttribute(mma_gemm<1,2>, cudaFuncAttributeMaxDynamicSharedMemorySize, SMEMTOT);
    cudaFuncSetAttribute(mma_gemm<0,1>, cudaFuncAttributeMaxDynamicSharedMemorySize, SMEMTOT);

    __half *phi_hi, *phi_lo, *W_hi, *q_hi;
    __half *kT_hi, *vT_hi, *kvT_hi;
    float *qkv, *bias, *kvp;
    cudaGetSymbolAddress((void**)&phi_hi, g_phi_hi);
    cudaGetSymbolAddress((void**)&phi_lo, g_phi_lo);
    cudaGetSymbolAddress((void**)&W_hi,   g_W_hi);
    cudaGetSymbolAddress((void**)&q_hi,   g_q_hi);
    cudaGetSymbolAddress((void**)&kT_hi,  g_kT_hi);
    cudaGetSymbolAddress((void**)&vT_hi,  g_vT_hi);
    cudaGetSymbolAddress((void**)&kvT_hi, g_kvT_hi);
    cudaGetSymbolAddress((void**)&qkv,    g_qkv);
    cudaGetSymbolAddress((void**)&bias,   g_bias);
    cudaGetSymbolAddress((void**)&kvp,    g_kvp);

    pack_phi<<<(Mm * Dd) / 1024, 256>>>(phi);
    pack_W<<<QKVC, 128>>>(Wq, bq, Wk, bk, Wv, bv);

    // qkv = phi @ Wcat^T + bias   (2-term A)
    mma_gemm<1,2><<<dim3(QKVC/128, Mm/128, 1), 256, SMEMTOT>>>(
        phi_hi, phi_lo, W_hi, Dd, Dd, 0, 0, 0,
        qkv, 0, QKVC, bias);

    rope_split<<<dim3(Mm/32, 4), 256>>>(coords, weights, Wrot);

    // kv split-K: kvp[b,chunk][e,d] = sum_{n in chunk} vT[e,n]*kT[d,n]  (1-term)
    mma_gemm<0,1><<<dim3(Dd/128, Dd/128, Bb*KVCH), 256, SMEMTOT>>>(
        vT_hi, nullptr, kT_hi, Nn/KVCH, Nn, 3,
        (size_t)Dd*Nn, (size_t)Dd*Nn,
        kvp, (size_t)Dd*Dd, Dd, nullptr);

    reduce_pack_kv<<<(Bb * Dd * Dd) / 512, 256>>>();

    // out[m,e] = sum_d q[m,d]*kvT[e,d]   (1-term)
    mma_gemm<0,1><<<dim3(Dd/128, Nn/128, Bb), 256, SMEMTOT>>>(
        q_hi, nullptr, kvT_hi, Dd, Dd, 0,
        (size_t)Nn*Dd, (size_t)Dd*Dd,
        out, (size_t)Nn*Dd, Dd, nullptr);
}

// round 9
// speedup vs baseline: 3.8267x; 1.1407x over previous
#include <cuda_runtime.h>
#include <cuda_fp16.h>
#include <math.h>
#include <stdint.h>

#define Bb 8
#define Nn 4096
#define Dd 512
#define Mm (Bb*Nn)      // 32768
#define QKVC 1536
#define KVCH 8          // split-K chunks for kv GEMM

// ---------------- scratch (__device__ globals; allocation-free rule) --------
__device__ __half g_phi_hi[(size_t)Mm*Dd];
__device__ __half g_phi_lo[(size_t)Mm*Dd];
__device__ __half g_W_hi[(size_t)QKVC*Dd];     // permuted rows (rope pairs adjacent)
__device__ float  g_bias[QKVC];                 // same permutation
__device__ __half g_q_hi[(size_t)Mm*Dd];
__device__ __half g_kT_hi[(size_t)Bb*Dd*Nn];
__device__ __half g_vT_hi[(size_t)Bb*Dd*Nn];
__device__ float  g_kvp[(size_t)Bb*KVCH*Dd*Dd]; // split-K partials
__device__ __half g_kvT_hi[(size_t)Bb*Dd*Dd];

// ---------------- helpers ----------------------------------------------------
__device__ __forceinline__ uint32_t smem_u32(const void* p) {
    uint32_t a;
    asm("{ .reg .u64 t; cvta.to.shared.u64 t, %1; cvt.u32.u64 %0, t; }" : "=r"(a) : "l"(p));
    return a;
}
__device__ __forceinline__ void cp16(uint32_t dst, const void* src) {
    asm volatile("cp.async.cg.shared.global [%0], [%1], 16;" :: "r"(dst), "l"(src) : "memory");
}
__device__ __forceinline__ void ldsm4(uint32_t* r, uint32_t addr) {
    asm volatile("ldmatrix.sync.aligned.m8n8.x4.shared.b16 {%0,%1,%2,%3}, [%4];"
                 : "=r"(r[0]), "=r"(r[1]), "=r"(r[2]), "=r"(r[3]) : "r"(addr));
}
__device__ __forceinline__ void mma16816(float* d, const uint32_t* a, const uint32_t* b) {
    asm volatile(
        "mma.sync.aligned.m16n8k16.row.col.f32.f16.f16.f32 "
        "{%0,%1,%2,%3}, {%4,%5,%6,%7}, {%8,%9}, {%0,%1,%2,%3};"
        : "+f"(d[0]), "+f"(d[1]), "+f"(d[2]), "+f"(d[3])
        : "r"(a[0]), "r"(a[1]), "r"(a[2]), "r"(a[3]), "r"(b[0]), "r"(b[1]));
}
__device__ __forceinline__ uint32_t packsplit(float v) {
    __half h = __float2half_rn(v);
    __half l = __float2half_rn(v - __half2float(h));
    return (uint32_t)__half_as_ushort(h) | ((uint32_t)__half_as_ushort(l) << 16);
}
__device__ __forceinline__ uint32_t pack2h(float a, float b) {
    return (uint32_t)__half_as_ushort(__float2half_rn(a)) |
           ((uint32_t)__half_as_ushort(__float2half_rn(b)) << 16);
}

#define RB 80            // row stride bytes (32 fp16 = 64B data + 16B pad)
#define STG (128*RB)     // 10240 B per operand stage
#define SLOT (2*STG)     // A+B per stage
#define SMEMTOT (4*SLOT) // 81920 B

// ---------------------------------------------------------------------------
// Generic warp-MMA fp16 GEMM (1-term A): D[m,n] = Ahi[m,:] . Bhi[n,:]
// Block tile 128x128x32, 8 warps, 4-stage cp.async ring.
// blockIdx.z = (batch << bzShift) | chunk.
// ---------------------------------------------------------------------------
__global__ __launch_bounds__(256, 2) void mma_gemm1(
    const __half* __restrict__ Ahi, const __half* __restrict__ Bhi,
    int Kchunk, int ldab, int bzShift, size_t aBS, size_t bBS,
    float* __restrict__ C, size_t cBS, int ldc)
{
    extern __shared__ __align__(16) char smem[];
    const uint32_t sbase = smem_u32(smem);
    const int tid  = threadIdx.x;
    const int lane = tid & 31;
    const int wid  = tid >> 5;
    const int wm   = wid >> 2;
    const int wn   = wid & 3;
    const int n0 = blockIdx.x * 128;
    const int m0 = blockIdx.y * 128;
    const int bz = blockIdx.z;
    const int b  = bz >> bzShift;
    const int koff = (bz & ((1 << bzShift) - 1)) * Kchunk;

    const int S = Kchunk >> 5;
    const __half* Ap = Ahi + (size_t)b * aBS;
    const __half* Bp = Bhi + (size_t)b * bBS;

    const int lr = tid >> 1;
    const int lc = (tid & 1) * 2;

    auto load = [&](int s) {
        int k0 = koff + (s << 5);
        uint32_t da = sbase + (s & 3) * SLOT;
        uint32_t db = da + STG;
        const __half* ag = Ap + (size_t)(m0 + lr) * ldab + k0 + lc * 8;
        cp16(da + lr * RB + lc * 16, ag);
        cp16(da + lr * RB + lc * 16 + 16, ag + 8);
        const __half* bg = Bp + (size_t)(n0 + lr) * ldab + k0 + lc * 8;
        cp16(db + lr * RB + lc * 16, bg);
        cp16(db + lr * RB + lc * 16 + 16, bg + 8);
        asm volatile("cp.async.commit_group;" ::: "memory");
    };

    const uint32_t laA = ((lane & 7) + ((lane >> 3) & 1) * 8) * RB + (lane >> 4) * 16;
    const uint32_t laB = ((lane & 7) + (lane >> 4) * 8) * RB + ((lane >> 3) & 1) * 16;

    float acc[4][4][4] = {};
    load(0); load(1); load(2);

    for (int s = 0; s < S; s++) {
        asm volatile("cp.async.wait_group 2;" ::: "memory");
        __syncthreads();
        if (s + 3 < S) load(s + 3);
        uint32_t sa  = sbase + (s & 3) * SLOT;
        uint32_t sbB = sa + STG;
#pragma unroll
        for (int ks = 0; ks < 2; ks++) {
            uint32_t a[4][4], bfr[2][4];
#pragma unroll
            for (int mf = 0; mf < 4; mf++)
                ldsm4(a[mf], sa + (wm * 64 + mf * 16) * RB + ks * 32 + laA);
#pragma unroll
            for (int bp = 0; bp < 2; bp++)
                ldsm4(bfr[bp], sbB + (wn * 32 + bp * 16) * RB + ks * 32 + laB);
#pragma unroll
            for (int mf = 0; mf < 4; mf++)
#pragma unroll
                for (int nf = 0; nf < 4; nf++)
                    mma16816(acc[mf][nf], a[mf], &bfr[nf >> 1][(nf & 1) * 2]);
        }
    }

    const int g = lane >> 2;
    const int cq = (lane & 3) * 2;
#pragma unroll
    for (int mf = 0; mf < 4; mf++)
#pragma unroll
        for (int nf = 0; nf < 4; nf++) {
            int row = m0 + wm * 64 + mf * 16 + g;
            int col = n0 + wn * 32 + nf * 8 + cq;
            float* dst = C + (size_t)bz * cBS + (size_t)row * ldc + col;
            *(float2*)dst = make_float2(acc[mf][nf][0], acc[mf][nf][1]);
            *(float2*)(dst + 8 * ldc) = make_float2(acc[mf][nf][2], acc[mf][nf][3]);
        }
}

// ---------------------------------------------------------------------------
// Fused QKV GEMM: qkv = phi @ Wperm^T + bias, then per-region epilogue:
//   region 0 (cols [0,512)):    q -> rope+scale -> g_q_hi row-major fp16
//   region 1 (cols [512,1024)): k -> rope -> smem transpose -> g_kT_hi [b,d,n]
//   region 2 (cols [1024,1536)):v -> *weights -> transpose -> g_vT_hi [b,d,n]
// W rows permuted so rope pair (h,h+256) = adjacent cols (2h,2h+1); d-order
// permutation cancels in the q.kv contraction.
// ---------------------------------------------------------------------------
__global__ __launch_bounds__(256, 2) void mma_gemm_qkv(
    const __half* __restrict__ Ahi, const __half* __restrict__ Alo,
    const __half* __restrict__ Bhi,
    const float* __restrict__ bias,
    const float* __restrict__ coords, const float* __restrict__ weights,
    const float* __restrict__ Wrot)
{
    extern __shared__ __align__(16) char smem[];
    const uint32_t sbase = smem_u32(smem);
    const int tid  = threadIdx.x;
    const int lane = tid & 31;
    const int wid  = tid >> 5;
    const int wm   = wid >> 2;
    const int wn   = wid & 3;
    const int n0 = blockIdx.x * 128;
    const int m0 = blockIdx.y * 128;

    const int KS = Dd >> 5;          // 16
    const int S  = 2 * KS;           // 32 (hi + lo A passes)
    const __half* Ap[2] = { Ahi, Alo };

    const int lr = tid >> 1;
    const int lc = (tid & 1) * 2;

    auto load = [&](int s) {
        int part = s >= KS;
        int k0 = (s - (part ? KS : 0)) << 5;
        const __half* A = Ap[part];
        uint32_t da = sbase + (s & 3) * SLOT;
        uint32_t db = da + STG;
        const __half* ag = A + (size_t)(m0 + lr) * Dd + k0 + lc * 8;
        cp16(da + lr * RB + lc * 16, ag);
        cp16(da + lr * RB + lc * 16 + 16, ag + 8);
        const __half* bg = Bhi + (size_t)(n0 + lr) * Dd + k0 + lc * 8;
        cp16(db + lr * RB + lc * 16, bg);
        cp16(db + lr * RB + lc * 16 + 16, bg + 8);
        asm volatile("cp.async.commit_group;" ::: "memory");
    };

    const uint32_t laA = ((lane & 7) + ((lane >> 3) & 1) * 8) * RB + (lane >> 4) * 16;
    const uint32_t laB = ((lane & 7) + (lane >> 4) * 8) * RB + ((lane >> 3) & 1) * 16;

    float acc[4][4][4] = {};
    load(0); load(1); load(2);

    for (int s = 0; s < S; s++) {
        asm volatile("cp.async.wait_group 2;" ::: "memory");
        __syncthreads();
        if (s + 3 < S) load(s + 3);
        uint32_t sa  = sbase + (s & 3) * SLOT;
        uint32_t sbB = sa + STG;
#pragma unroll
        for (int ks = 0; ks < 2; ks++) {
            uint32_t a[4][4], bfr[2][4];
#pragma unroll
            for (int mf = 0; mf < 4; mf++)
                ldsm4(a[mf], sa + (wm * 64 + mf * 16) * RB + ks * 32 + laA);
#pragma unroll
            for (int bp = 0; bp < 2; bp++)
                ldsm4(bfr[bp], sbB + (wn * 32 + bp * 16) * RB + ks * 32 + laB);
#pragma unroll
            for (int mf = 0; mf < 4; mf++)
#pragma unroll
                for (int nf = 0; nf < 4; nf++)
                    mma16816(acc[mf][nf], a[mf], &bfr[nf >> 1][(nf & 1) * 2]);
        }
    }

    // drain pending cp.async before smem reuse
    asm volatile("cp.async.wait_group 0;" ::: "memory");
    __syncthreads();

    const int g = lane >> 2;
    const int cq = (lane & 3) * 2;
    const int region = n0 >> 9;      // 0 q, 1 k, 2 v
    const float scale = 0.04419417382415922f;   // 1/sqrt(512)

    if (region == 0) {
        // q: rope + scale, direct row-major fp16 store
#pragma unroll
        for (int mf = 0; mf < 4; mf++) {
            int r0 = m0 + wm * 64 + mf * 16 + g;
            float cx0 = coords[r0*3], cy0 = coords[r0*3+1], cz0 = coords[r0*3+2];
            float cx1 = coords[(r0+8)*3], cy1 = coords[(r0+8)*3+1], cz1 = coords[(r0+8)*3+2];
#pragma unroll
            for (int nf = 0; nf < 4; nf++) {
                int col = n0 + wn * 32 + nf * 8 + cq;
                int h = col >> 1;
                float w0 = Wrot[h*3], w1 = Wrot[h*3+1], w2 = Wrot[h*3+2];
                float b0 = bias[col], b1 = bias[col+1];
                float s0, c0, s1, c1;
                __sincosf(cx0*w0 + cy0*w1 + cz0*w2, &s0, &c0);
                __sincosf(cx1*w0 + cy1*w1 + cz1*w2, &s1, &c1);
                float qa = acc[mf][nf][0] + b0, qb = acc[mf][nf][1] + b1;
                *(uint32_t*)(g_q_hi + (size_t)r0*Dd + col) =
                    pack2h((qa*c0 - qb*s0)*scale, (qa*s0 + qb*c0)*scale);
                qa = acc[mf][nf][2] + b0; qb = acc[mf][nf][3] + b1;
                *(uint32_t*)(g_q_hi + (size_t)(r0+8)*Dd + col) =
                    pack2h((qa*c1 - qb*s1)*scale, (qa*s1 + qb*c1)*scale);
            }
        }
    } else {
        uint16_t (*st)[136] = (uint16_t(*)[136])smem;
        const int cbase = (region == 1) ? 512 : 1024;
        if (region == 1) {
#pragma unroll
            for (int mf = 0; mf < 4; mf++) {
                int r0 = m0 + wm * 64 + mf * 16 + g;
                int lr0 = r0 - m0;
                float cx0 = coords[r0*3], cy0 = coords[r0*3+1], cz0 = coords[r0*3+2];
                float cx1 = coords[(r0+8)*3], cy1 = coords[(r0+8)*3+1], cz1 = coords[(r0+8)*3+2];
#pragma unroll
                for (int nf = 0; nf < 4; nf++) {
                    int col = n0 + wn * 32 + nf * 8 + cq;
                    int h = (col - 512) >> 1;
                    int lcol = col - n0;
                    float w0 = Wrot[h*3], w1 = Wrot[h*3+1], w2 = Wrot[h*3+2];
                    float b0 = bias[col], b1 = bias[col+1];
                    float s0, c0, s1, c1;
                    __sincosf(cx0*w0 + cy0*w1 + cz0*w2, &s0, &c0);
                    __sincosf(cx1*w0 + cy1*w1 + cz1*w2, &s1, &c1);
                    float ka = acc[mf][nf][0] + b0, kb = acc[mf][nf][1] + b1;
                    st[lcol][lr0]     = __half_as_ushort(__float2half_rn(ka*c0 - kb*s0));
                    st[lcol+1][lr0]   = __half_as_ushort(__float2half_rn(ka*s0 + kb*c0));
                    ka = acc[mf][nf][2] + b0; kb = acc[mf][nf][3] + b1;
                    st[lcol][lr0+8]   = __half_as_ushort(__float2half_rn(ka*c1 - kb*s1));
                    st[lcol+1][lr0+8] = __half_as_ushort(__float2half_rn(ka*s1 + kb*c1));
                }
            }
        } else {
#pragma unroll
            for (int mf = 0; mf < 4; mf++) {
                int r0 = m0 + wm * 64 + mf * 16 + g;
                int lr0 = r0 - m0;
                float wg0 = weights[r0], wg1 = weights[r0 + 8];
#pragma unroll
                for (int nf = 0; nf < 4; nf++) {
                    int col = n0 + wn * 32 + nf * 8 + cq;
                    int lcol = col - n0;
                    float b0 = bias[col], b1 = bias[col+1];
                    st[lcol][lr0]     = __half_as_ushort(__float2half_rn((acc[mf][nf][0]+b0)*wg0));
                    st[lcol+1][lr0]   = __half_as_ushort(__float2half_rn((acc[mf][nf][1]+b1)*wg0));
                    st[lcol][lr0+8]   = __half_as_ushort(__float2half_rn((acc[mf][nf][2]+b0)*wg1));
                    st[lcol+1][lr0+8] = __half_as_ushort(__float2half_rn((acc[mf][nf][3]+b1)*wg1));
                }
            }
        }
        __syncthreads();
        // transposed coalesced write: [b, d, n]
        const int dl = tid >> 1;
        const int j0 = (tid & 1) * 64;
        const int bidx = m0 >> 12;
        const int dcol = (n0 - cbase) + dl;
        __half* dstb = (region == 1) ? g_kT_hi : g_vT_hi;
        __half* dst = dstb + ((size_t)bidx * Dd + dcol) * Nn + (m0 & 4095) + j0;
#pragma unroll
        for (int k = 0; k < 8; k++)
            *(uint4*)(dst + k * 8) = *(uint4*)&st[dl][j0 + k * 8];
    }
}

// ---------------------------------------------------------------------------
// Sum KVCH split-K partial kv slices, emit fp16 hi (B operand of GEMM3).
// ---------------------------------------------------------------------------
__global__ __launch_bounds__(256) void reduce_pack_kv()
{
    size_t i = ((size_t)blockIdx.x * 256 + threadIdx.x) * 2;
    size_t b   = i >> 18;
    size_t off = i & 262143;
    const float* base = g_kvp + ((size_t)b * KVCH) * 262144 + off;
    float s0 = 0.f, s1 = 0.f;
#pragma unroll
    for (int c = 0; c < KVCH; c++) {
        float2 v = *(const float2*)(base + (size_t)c * 262144);
        s0 += v.x; s1 += v.y;
    }
    size_t o = (size_t)b * 262144 + off;
    *(uint32_t*)(g_kvT_hi + o) = pack2h(s0, s1);
}

// ---------------------------------------------------------------------------
__global__ __launch_bounds__(256) void pack_phi(const float* __restrict__ phi)
{
    size_t i = ((size_t)blockIdx.x * 256 + threadIdx.x) * 4;
    float4 x = *(const float4*)(phi + i);
    uint32_t a = packsplit(x.x), b = packsplit(x.y), c = packsplit(x.z), d = packsplit(x.w);
    *(uint32_t*)(g_phi_hi + i)     = (a & 0xffffu) | (b << 16);
    *(uint32_t*)(g_phi_hi + i + 2) = (c & 0xffffu) | (d << 16);
    *(uint32_t*)(g_phi_lo + i)     = (a >> 16) | (b & 0xffff0000u);
    *(uint32_t*)(g_phi_lo + i + 2) = (c >> 16) | (d & 0xffff0000u);
}

// Permuted: q/k regions interleave rope pairs -> out row 2h <- h, 2h+1 <- h+256
__global__ __launch_bounds__(128) void pack_W(
    const float* __restrict__ Wq, const float* __restrict__ bq,
    const float* __restrict__ Wk, const float* __restrict__ bk,
    const float* __restrict__ Wv, const float* __restrict__ bv)
{
    int r = blockIdx.x, t = threadIdx.x;
    const float* src; const float* bs; int sr;
    if (r < 512)       { src = Wq; bs = bq; int h = r >> 1;         sr = (r & 1) ? h + 256 : h; }
    else if (r < 1024) { src = Wk; bs = bk; int h = (r - 512) >> 1; sr = ((r - 512) & 1) ? h + 256 : h; }
    else               { src = Wv; bs = bv; sr = r - 1024; }
    float4 x = *(const float4*)(src + (size_t)sr * Dd + t * 4);
    size_t o = (size_t)r * Dd + t * 4;
    *(uint32_t*)(g_W_hi + o)     = pack2h(x.x, x.y);
    *(uint32_t*)(g_W_hi + o + 2) = pack2h(x.z, x.w);
    if (t == 0) g_bias[r] = bs[sr];
}

// ---------------------------------------------------------------------------
extern "C" void kernel_launch(void* const* d_in, const int* in_sizes, int n_in,
                              void* d_out, int out_size)
{
    (void)in_sizes; (void)n_in; (void)out_size;
    const float* phi     = (const float*)d_in[0];
    const float* coords  = (const float*)d_in[1];
    const float* weights = (const float*)d_in[2];
    const float* Wq      = (const float*)d_in[3];
    const float* bq      = (const float*)d_in[4];
    const float* Wk      = (const float*)d_in[5];
    const float* bk      = (const float*)d_in[6];
    const float* Wv      = (const float*)d_in[7];
    const float* bv      = (const float*)d_in[8];
    const float* Wrot    = (const float*)d_in[9];
    float* out = (float*)d_out;

    cudaFuncSetAttribute(mma_gemm1,    cudaFuncAttributeMaxDynamicSharedMemorySize, SMEMTOT);
    cudaFuncSetAttribute(mma_gemm_qkv, cudaFuncAttributeMaxDynamicSharedMemorySize, SMEMTOT);

    __half *phi_hi, *phi_lo, *W_hi, *q_hi, *kT_hi, *vT_hi, *kvT_hi;
    float *bias, *kvp;
    cudaGetSymbolAddress((void**)&phi_hi, g_phi_hi);
    cudaGetSymbolAddress((void**)&phi_lo, g_phi_lo);
    cudaGetSymbolAddress((void**)&W_hi,   g_W_hi);
    cudaGetSymbolAddress((void**)&q_hi,   g_q_hi);
    cudaGetSymbolAddress((void**)&kT_hi,  g_kT_hi);
    cudaGetSymbolAddress((void**)&vT_hi,  g_vT_hi);
    cudaGetSymbolAddress((void**)&kvT_hi, g_kvT_hi);
    cudaGetSymbolAddress((void**)&bias,   g_bias);
    cudaGetSymbolAddress((void**)&kvp,    g_kvp);

    pack_phi<<<(Mm * Dd) / 1024, 256>>>(phi);
    pack_W<<<QKVC, 128>>>(Wq, bq, Wk, bk, Wv, bv);

    // fused: qkv GEMM + bias + rope/scale/weights + fp16 pack + k/v transpose
    mma_gemm_qkv<<<dim3(QKVC/128, Mm/128, 1), 256, SMEMTOT>>>(
        phi_hi, phi_lo, W_hi, bias, coords, weights, Wrot);

    // kv split-K: kvp[b,chunk][e,d] = sum_{n in chunk} vT[e,n]*kT[d,n]
    mma_gemm1<<<dim3(Dd/128, Dd/128, Bb*KVCH), 256, SMEMTOT>>>(
        vT_hi, kT_hi, Nn/KVCH, Nn, 3,
        (size_t)Dd*Nn, (size_t)Dd*Nn,
        kvp, (size_t)Dd*Dd, Dd);

    reduce_pack_kv<<<(Bb * Dd * Dd) / 512, 256>>>();

    // out[m,e] = sum_d q[m,d]*kvT[e,d]
    mma_gemm1<<<dim3(Dd/128, Nn/128, Bb), 256, SMEMTOT>>>(
        q_hi, kvT_hi, Dd, Dd, 0,
        (size_t)Nn*Dd, (size_t)Dd*Dd,
        out, (size_t)Nn*Dd, Dd);
}

// round 10
// speedup vs baseline: 5.6096x; 1.4659x over previous
#include <cuda_runtime.h>
#include <cuda_fp16.h>
#include <math.h>
#include <stdint.h>

#define Bb 8
#define Nn 4096
#define Dd 512
#define Mm (Bb*Nn)      // 32768
#define QKVC 1536
#define KVCH 8          // split-K chunks for kv GEMM

// ---------------- scratch (__device__ globals; allocation-free rule) --------
__device__ __half g_phi_hi[(size_t)Mm*Dd];
__device__ __half g_W_hi[(size_t)QKVC*Dd];     // permuted rows (rope pairs adjacent)
__device__ float  g_bias[QKVC];                 // same permutation
__device__ __half g_q_hi[(size_t)Mm*Dd];
__device__ __half g_kT_hi[(size_t)Bb*Dd*Nn];
__device__ __half g_vT_hi[(size_t)Bb*Dd*Nn];
__device__ float  g_kvp[(size_t)Bb*KVCH*Dd*Dd]; // split-K partials
__device__ __half g_kvT_hi[(size_t)Bb*Dd*Dd];

// ---------------- helpers ----------------------------------------------------
__device__ __forceinline__ uint32_t smem_u32(const void* p) {
    uint32_t a;
    asm("{ .reg .u64 t; cvta.to.shared.u64 t, %1; cvt.u32.u64 %0, t; }" : "=r"(a) : "l"(p));
    return a;
}
__device__ __forceinline__ void cp16(uint32_t dst, const void* src) {
    asm volatile("cp.async.cg.shared.global [%0], [%1], 16;" :: "r"(dst), "l"(src) : "memory");
}
__device__ __forceinline__ void ldsm4(uint32_t* r, uint32_t addr) {
    asm volatile("ldmatrix.sync.aligned.m8n8.x4.shared.b16 {%0,%1,%2,%3}, [%4];"
                 : "=r"(r[0]), "=r"(r[1]), "=r"(r[2]), "=r"(r[3]) : "r"(addr));
}
__device__ __forceinline__ void mma16816(float* d, const uint32_t* a, const uint32_t* b) {
    asm volatile(
        "mma.sync.aligned.m16n8k16.row.col.f32.f16.f16.f32 "
        "{%0,%1,%2,%3}, {%4,%5,%6,%7}, {%8,%9}, {%0,%1,%2,%3};"
        : "+f"(d[0]), "+f"(d[1]), "+f"(d[2]), "+f"(d[3])
        : "r"(a[0]), "r"(a[1]), "r"(a[2]), "r"(a[3]), "r"(b[0]), "r"(b[1]));
}
__device__ __forceinline__ uint32_t pack2h(float a, float b) {
    return (uint32_t)__half_as_ushort(__float2half_rn(a)) |
           ((uint32_t)__half_as_ushort(__float2half_rn(b)) << 16);
}

#define RB 80            // row stride bytes (32 fp16 = 64B data + 16B pad)
#define STG (128*RB)     // 10240 B per operand stage
#define SLOT (2*STG)     // A+B per stage
#define SMEMTOT (4*SLOT) // 81920 B

// ---------------------------------------------------------------------------
// Generic warp-MMA fp16 GEMM: D[m,n] = Ahi[m,:] . Bhi[n,:]
// Block tile 128x128x32, 8 warps, 4-stage cp.async ring.
// blockIdx.z = (batch << bzShift) | chunk.
// ---------------------------------------------------------------------------
__global__ __launch_bounds__(256, 2) void mma_gemm1(
    const __half* __restrict__ Ahi, const __half* __restrict__ Bhi,
    int Kchunk, int ldab, int bzShift, size_t aBS, size_t bBS,
    float* __restrict__ C, size_t cBS, int ldc)
{
    extern __shared__ __align__(16) char smem[];
    const uint32_t sbase = smem_u32(smem);
    const int tid  = threadIdx.x;
    const int lane = tid & 31;
    const int wid  = tid >> 5;
    const int wm   = wid >> 2;
    const int wn   = wid & 3;
    const int n0 = blockIdx.x * 128;
    const int m0 = blockIdx.y * 128;
    const int bz = blockIdx.z;
    const int b  = bz >> bzShift;
    const int koff = (bz & ((1 << bzShift) - 1)) * Kchunk;

    const int S = Kchunk >> 5;
    const __half* Ap = Ahi + (size_t)b * aBS;
    const __half* Bp = Bhi + (size_t)b * bBS;

    const int lr = tid >> 1;
    const int lc = (tid & 1) * 2;

    auto load = [&](int s) {
        int k0 = koff + (s << 5);
        uint32_t da = sbase + (s & 3) * SLOT;
        uint32_t db = da + STG;
        const __half* ag = Ap + (size_t)(m0 + lr) * ldab + k0 + lc * 8;
        cp16(da + lr * RB + lc * 16, ag);
        cp16(da + lr * RB + lc * 16 + 16, ag + 8);
        const __half* bg = Bp + (size_t)(n0 + lr) * ldab + k0 + lc * 8;
        cp16(db + lr * RB + lc * 16, bg);
        cp16(db + lr * RB + lc * 16 + 16, bg + 8);
        asm volatile("cp.async.commit_group;" ::: "memory");
    };

    const uint32_t laA = ((lane & 7) + ((lane >> 3) & 1) * 8) * RB + (lane >> 4) * 16;
    const uint32_t laB = ((lane & 7) + (lane >> 4) * 8) * RB + ((lane >> 3) & 1) * 16;

    float acc[4][4][4] = {};
    load(0); load(1); load(2);

    for (int s = 0; s < S; s++) {
        asm volatile("cp.async.wait_group 2;" ::: "memory");
        __syncthreads();
        if (s + 3 < S) load(s + 3);
        uint32_t sa  = sbase + (s & 3) * SLOT;
        uint32_t sbB = sa + STG;
#pragma unroll
        for (int ks = 0; ks < 2; ks++) {
            uint32_t a[4][4], bfr[2][4];
#pragma unroll
            for (int mf = 0; mf < 4; mf++)
                ldsm4(a[mf], sa + (wm * 64 + mf * 16) * RB + ks * 32 + laA);
#pragma unroll
            for (int bp = 0; bp < 2; bp++)
                ldsm4(bfr[bp], sbB + (wn * 32 + bp * 16) * RB + ks * 32 + laB);
#pragma unroll
            for (int mf = 0; mf < 4; mf++)
#pragma unroll
                for (int nf = 0; nf < 4; nf++)
                    mma16816(acc[mf][nf], a[mf], &bfr[nf >> 1][(nf & 1) * 2]);
        }
    }

    const int g = lane >> 2;
    const int cq = (lane & 3) * 2;
#pragma unroll
    for (int mf = 0; mf < 4; mf++)
#pragma unroll
        for (int nf = 0; nf < 4; nf++) {
            int row = m0 + wm * 64 + mf * 16 + g;
            int col = n0 + wn * 32 + nf * 8 + cq;
            float* dst = C + (size_t)bz * cBS + (size_t)row * ldc + col;
            *(float2*)dst = make_float2(acc[mf][nf][0], acc[mf][nf][1]);
            *(float2*)(dst + 8 * ldc) = make_float2(acc[mf][nf][2], acc[mf][nf][3]);
        }
}

// ---------------------------------------------------------------------------
// Fused QKV GEMM (1-term A): qkv = phi @ Wperm^T + bias, per-region epilogue:
//   region 0 (cols [0,512)):    q -> rope+scale -> g_q_hi row-major fp16
//   region 1 (cols [512,1024)): k -> rope -> smem transpose -> g_kT_hi [b,d,n]
//   region 2 (cols [1024,1536)):v -> *weights -> transpose -> g_vT_hi [b,d,n]
// W rows permuted so rope pair (h,h+256) = adjacent cols (2h,2h+1); d-order
// permutation cancels in the q.kv contraction.
// ---------------------------------------------------------------------------
__global__ __launch_bounds__(256, 2) void mma_gemm_qkv(
    const __half* __restrict__ Ahi, const __half* __restrict__ Bhi,
    const float* __restrict__ bias,
    const float* __restrict__ coords, const float* __restrict__ weights,
    const float* __restrict__ Wrot)
{
    extern __shared__ __align__(16) char smem[];
    const uint32_t sbase = smem_u32(smem);
    const int tid  = threadIdx.x;
    const int lane = tid & 31;
    const int wid  = tid >> 5;
    const int wm   = wid >> 2;
    const int wn   = wid & 3;
    const int n0 = blockIdx.x * 128;
    const int m0 = blockIdx.y * 128;

    const int S = Dd >> 5;           // 16
    const int lr = tid >> 1;
    const int lc = (tid & 1) * 2;

    auto load = [&](int s) {
        int k0 = s << 5;
        uint32_t da = sbase + (s & 3) * SLOT;
        uint32_t db = da + STG;
        const __half* ag = Ahi + (size_t)(m0 + lr) * Dd + k0 + lc * 8;
        cp16(da + lr * RB + lc * 16, ag);
        cp16(da + lr * RB + lc * 16 + 16, ag + 8);
        const __half* bg = Bhi + (size_t)(n0 + lr) * Dd + k0 + lc * 8;
        cp16(db + lr * RB + lc * 16, bg);
        cp16(db + lr * RB + lc * 16 + 16, bg + 8);
        asm volatile("cp.async.commit_group;" ::: "memory");
    };

    const uint32_t laA = ((lane & 7) + ((lane >> 3) & 1) * 8) * RB + (lane >> 4) * 16;
    const uint32_t laB = ((lane & 7) + (lane >> 4) * 8) * RB + ((lane >> 3) & 1) * 16;

    float acc[4][4][4] = {};
    load(0); load(1); load(2);

    for (int s = 0; s < S; s++) {
        asm volatile("cp.async.wait_group 2;" ::: "memory");
        __syncthreads();
        if (s + 3 < S) load(s + 3);
        uint32_t sa  = sbase + (s & 3) * SLOT;
        uint32_t sbB = sa + STG;
#pragma unroll
        for (int ks = 0; ks < 2; ks++) {
            uint32_t a[4][4], bfr[2][4];
#pragma unroll
            for (int mf = 0; mf < 4; mf++)
                ldsm4(a[mf], sa + (wm * 64 + mf * 16) * RB + ks * 32 + laA);
#pragma unroll
            for (int bp = 0; bp < 2; bp++)
                ldsm4(bfr[bp], sbB + (wn * 32 + bp * 16) * RB + ks * 32 + laB);
#pragma unroll
            for (int mf = 0; mf < 4; mf++)
#pragma unroll
                for (int nf = 0; nf < 4; nf++)
                    mma16816(acc[mf][nf], a[mf], &bfr[nf >> 1][(nf & 1) * 2]);
        }
    }

    // drain pending cp.async before smem reuse
    asm volatile("cp.async.wait_group 0;" ::: "memory");
    __syncthreads();

    const int g = lane >> 2;
    const int cq = (lane & 3) * 2;
    const int region = n0 >> 9;      // 0 q, 1 k, 2 v
    const float scale = 0.04419417382415922f;   // 1/sqrt(512)

    if (region == 0) {
        // q: rope + scale, direct row-major fp16 store
#pragma unroll
        for (int mf = 0; mf < 4; mf++) {
            int r0 = m0 + wm * 64 + mf * 16 + g;
            float cx0 = coords[r0*3], cy0 = coords[r0*3+1], cz0 = coords[r0*3+2];
            float cx1 = coords[(r0+8)*3], cy1 = coords[(r0+8)*3+1], cz1 = coords[(r0+8)*3+2];
#pragma unroll
            for (int nf = 0; nf < 4; nf++) {
                int col = n0 + wn * 32 + nf * 8 + cq;
                int h = col >> 1;
                float w0 = Wrot[h*3], w1 = Wrot[h*3+1], w2 = Wrot[h*3+2];
                float b0 = bias[col], b1 = bias[col+1];
                float s0, c0, s1, c1;
                __sincosf(cx0*w0 + cy0*w1 + cz0*w2, &s0, &c0);
                __sincosf(cx1*w0 + cy1*w1 + cz1*w2, &s1, &c1);
                float qa = acc[mf][nf][0] + b0, qb = acc[mf][nf][1] + b1;
                *(uint32_t*)(g_q_hi + (size_t)r0*Dd + col) =
                    pack2h((qa*c0 - qb*s0)*scale, (qa*s0 + qb*c0)*scale);
                qa = acc[mf][nf][2] + b0; qb = acc[mf][nf][3] + b1;
                *(uint32_t*)(g_q_hi + (size_t)(r0+8)*Dd + col) =
                    pack2h((qa*c1 - qb*s1)*scale, (qa*s1 + qb*c1)*scale);
            }
        }
    } else {
        uint16_t (*st)[136] = (uint16_t(*)[136])smem;
        const int cbase = (region == 1) ? 512 : 1024;
        if (region == 1) {
#pragma unroll
            for (int mf = 0; mf < 4; mf++) {
                int r0 = m0 + wm * 64 + mf * 16 + g;
                int lr0 = r0 - m0;
                float cx0 = coords[r0*3], cy0 = coords[r0*3+1], cz0 = coords[r0*3+2];
                float cx1 = coords[(r0+8)*3], cy1 = coords[(r0+8)*3+1], cz1 = coords[(r0+8)*3+2];
#pragma unroll
                for (int nf = 0; nf < 4; nf++) {
                    int col = n0 + wn * 32 + nf * 8 + cq;
                    int h = (col - 512) >> 1;
                    int lcol = col - n0;
                    float w0 = Wrot[h*3], w1 = Wrot[h*3+1], w2 = Wrot[h*3+2];
                    float b0 = bias[col], b1 = bias[col+1];
                    float s0, c0, s1, c1;
                    __sincosf(cx0*w0 + cy0*w1 + cz0*w2, &s0, &c0);
                    __sincosf(cx1*w0 + cy1*w1 + cz1*w2, &s1, &c1);
                    float ka = acc[mf][nf][0] + b0, kb = acc[mf][nf][1] + b1;
                    st[lcol][lr0]     = __half_as_ushort(__float2half_rn(ka*c0 - kb*s0));
                    st[lcol+1][lr0]   = __half_as_ushort(__float2half_rn(ka*s0 + kb*c0));
                    ka = acc[mf][nf][2] + b0; kb = acc[mf][nf][3] + b1;
                    st[lcol][lr0+8]   = __half_as_ushort(__float2half_rn(ka*c1 - kb*s1));
                    st[lcol+1][lr0+8] = __half_as_ushort(__float2half_rn(ka*s1 + kb*c1));
                }
            }
        } else {
#pragma unroll
            for (int mf = 0; mf < 4; mf++) {
                int r0 = m0 + wm * 64 + mf * 16 + g;
                int lr0 = r0 - m0;
                float wg0 = weights[r0], wg1 = weights[r0 + 8];
#pragma unroll
                for (int nf = 0; nf < 4; nf++) {
                    int col = n0 + wn * 32 + nf * 8 + cq;
                    int lcol = col - n0;
                    float b0 = bias[col], b1 = bias[col+1];
                    st[lcol][lr0]     = __half_as_ushort(__float2half_rn((acc[mf][nf][0]+b0)*wg0));
                    st[lcol+1][lr0]   = __half_as_ushort(__float2half_rn((acc[mf][nf][1]+b1)*wg0));
                    st[lcol][lr0+8]   = __half_as_ushort(__float2half_rn((acc[mf][nf][2]+b0)*wg1));
                    st[lcol+1][lr0+8] = __half_as_ushort(__float2half_rn((acc[mf][nf][3]+b1)*wg1));
                }
            }
        }
        __syncthreads();
        // transposed coalesced write: [b, d, n]
        const int dl = tid >> 1;
        const int j0 = (tid & 1) * 64;
        const int bidx = m0 >> 12;
        const int dcol = (n0 - cbase) + dl;
        __half* dstb = (region == 1) ? g_kT_hi : g_vT_hi;
        __half* dst = dstb + ((size_t)bidx * Dd + dcol) * Nn + (m0 & 4095) + j0;
#pragma unroll
        for (int k = 0; k < 8; k++)
            *(uint4*)(dst + k * 8) = *(uint4*)&st[dl][j0 + k * 8];
    }
}

// ---------------------------------------------------------------------------
// Sum KVCH split-K partial kv slices, emit fp16 hi (B operand of GEMM3).
// ---------------------------------------------------------------------------
__global__ __launch_bounds__(256) void reduce_pack_kv()
{
    size_t i = ((size_t)blockIdx.x * 256 + threadIdx.x) * 2;
    size_t b   = i >> 18;
    size_t off = i & 262143;
    const float* base = g_kvp + ((size_t)b * KVCH) * 262144 + off;
    float s0 = 0.f, s1 = 0.f;
#pragma unroll
    for (int c = 0; c < KVCH; c++) {
        float2 v = *(const float2*)(base + (size_t)c * 262144);
        s0 += v.x; s1 += v.y;
    }
    size_t o = (size_t)b * 262144 + off;
    *(uint32_t*)(g_kvT_hi + o) = pack2h(s0, s1);
}

// ---------------------------------------------------------------------------
__global__ __launch_bounds__(256) void pack_phi(const float* __restrict__ phi)
{
    size_t i = ((size_t)blockIdx.x * 256 + threadIdx.x) * 4;
    float4 x = *(const float4*)(phi + i);
    *(uint32_t*)(g_phi_hi + i)     = pack2h(x.x, x.y);
    *(uint32_t*)(g_phi_hi + i + 2) = pack2h(x.z, x.w);
}

// Permuted: q/k regions interleave rope pairs -> out row 2h <- h, 2h+1 <- h+256
__global__ __launch_bounds__(128) void pack_W(
    const float* __restrict__ Wq, const float* __restrict__ bq,
    const float* __restrict__ Wk, const float* __restrict__ bk,
    const float* __restrict__ Wv, const float* __restrict__ bv)
{
    int r = blockIdx.x, t = threadIdx.x;
    const float* src; const float* bs; int sr;
    if (r < 512)       { src = Wq; bs = bq; int h = r >> 1;         sr = (r & 1) ? h + 256 : h; }
    else if (r < 1024) { src = Wk; bs = bk; int h = (r - 512) >> 1; sr = ((r - 512) & 1) ? h + 256 : h; }
    else               { src = Wv; bs = bv; sr = r - 1024; }
    float4 x = *(const float4*)(src + (size_t)sr * Dd + t * 4);
    size_t o = (size_t)r * Dd + t * 4;
    *(uint32_t*)(g_W_hi + o)     = pack2h(x.x, x.y);
    *(uint32_t*)(g_W_hi + o + 2) = pack2h(x.z, x.w);
    if (t == 0) g_bias[r] = bs[sr];
}

// ---------------------------------------------------------------------------
extern "C" void kernel_launch(void* const* d_in, const int* in_sizes, int n_in,
                              void* d_out, int out_size)
{
    (void)in_sizes; (void)n_in; (void)out_size;
    const float* phi     = (const float*)d_in[0];
    const float* coords  = (const float*)d_in[1];
    const float* weights = (const float*)d_in[2];
    const float* Wq      = (const float*)d_in[3];
    const float* bq      = (const float*)d_in[4];
    const float* Wk      = (const float*)d_in[5];
    const float* bk      = (const float*)d_in[6];
    const float* Wv      = (const float*)d_in[7];
    const float* bv      = (const float*)d_in[8];
    const float* Wrot    = (const float*)d_in[9];
    float* out = (float*)d_out;

    cudaFuncSetAttribute(mma_gemm1,    cudaFuncAttributeMaxDynamicSharedMemorySize, SMEMTOT);
    cudaFuncSetAttribute(mma_gemm_qkv, cudaFuncAttributeMaxDynamicSharedMemorySize, SMEMTOT);

    __half *phi_hi, *W_hi, *q_hi, *kT_hi, *vT_hi, *kvT_hi;
    float *bias, *kvp;
    cudaGetSymbolAddress((void**)&phi_hi, g_phi_hi);
    cudaGetSymbolAddress((void**)&W_hi,   g_W_hi);
    cudaGetSymbolAddress((void**)&q_hi,   g_q_hi);
    cudaGetSymbolAddress((void**)&kT_hi,  g_kT_hi);
    cudaGetSymbolAddress((void**)&vT_hi,  g_vT_hi);
    cudaGetSymbolAddress((void**)&kvT_hi, g_kvT_hi);
    cudaGetSymbolAddress((void**)&bias,   g_bias);
    cudaGetSymbolAddress((void**)&kvp,    g_kvp);

    pack_phi<<<(Mm * Dd) / 1024, 256>>>(phi);
    pack_W<<<QKVC, 128>>>(Wq, bq, Wk, bk, Wv, bv);

    // fused: qkv GEMM + bias + rope/scale/weights + fp16 pack + k/v transpose
    mma_gemm_qkv<<<dim3(QKVC/128, Mm/128, 1), 256, SMEMTOT>>>(
        phi_hi, W_hi, bias, coords, weights, Wrot);

    // kv split-K: kvp[b,chunk][e,d] = sum_{n in chunk} vT[e,n]*kT[d,n]
    mma_gemm1<<<dim3(Dd/128, Dd/128, Bb*KVCH), 256, SMEMTOT>>>(
        vT_hi, kT_hi, Nn/KVCH, Nn, 3,
        (size_t)Dd*Nn, (size_t)Dd*Nn,
        kvp, (size_t)Dd*Dd, Dd);

    reduce_pack_kv<<<(Bb * Dd * Dd) / 512, 256>>>();

    // out[m,e] = sum_d q[m,d]*kvT[e,d]
    mma_gemm1<<<dim3(Dd/128, Nn/128, Bb), 256, SMEMTOT>>>(
        q_hi, kvT_hi, Dd, Dd, 0,
        (size_t)Nn*Dd, (size_t)Dd*Dd,
        out, (size_t)Nn*Dd, Dd);
}